// round 14
// baseline (speedup 1.0000x reference)
#include <cuda_runtime.h>
#include <cuda_fp16.h>
#include <math.h>
#include <stdint.h>
#include <string.h>

#define TTOK 2048
#define DMOD 1024
#define FDIM 4096
#define SEQ  1024
#define NBAT 2
#define NH   16
#define HDM  64
#define NE   8
#define VOC  32000
#define NL   3

// ---------------- scratch (static device globals; no allocation) ----------------
__device__ __half g_qkvw_h[NL*DMOD*3072], g_qkvw_l[NL*DMOD*3072];
__device__ float  g_bqkv  [NL*3072];
__device__ __half g_wo_h [NL*DMOD*DMOD], g_wo_l [NL*DMOD*DMOD];
__device__ __half g_w1_h [NL*DMOD*FDIM], g_w1_l [NL*DMOD*FDIM];
__device__ __half g_w2_h [NL*FDIM*DMOD], g_w2_l [NL*FDIM*DMOD];
__device__ __half g_ew1_h[NE*DMOD*FDIM];
__device__ __half g_ew2_h[NE*FDIM*DMOD];
__device__ __half g_ow_h [DMOD*VOC];
// activations split hi/lo
__device__ __half g_x_h  [TTOK*DMOD], g_x_l  [TTOK*DMOD];
__device__ __half g_qkv_h[TTOK*3072], g_qkv_l[TTOK*3072];
__device__ __half g_ao_h [TTOK*DMOD], g_ao_l [TTOK*DMOD];
__device__ __half g_ffh_h[TTOK*FDIM], g_ffh_l[TTOK*FDIM];
__device__ __half g_mh_h [NE*TTOK*FDIM], g_mh_l [NE*TTOK*FDIM];
__device__ __half g_xn_h [TTOK*DMOD], g_xn_l [TTOK*DMOD];
// fp32 intermediates
__device__ float  g_xf  [TTOK*DMOD];
__device__ float  g_t1f [TTOK*DMOD];
__device__ float  g_moef[TTOK*DMOD];
__device__ float  g_xnf [TTOK*DMOD];
__device__ int    g_cnt [NE];
__device__ int    g_perm[NE*TTOK];
__device__ float  g_pw  [NE*TTOK];

// ---------------- PTX helpers ----------------
__device__ __forceinline__ uint32_t smem_u32(const void* p) {
    return (uint32_t)__cvta_generic_to_shared(p);
}
__device__ __forceinline__ void cp16(void* dst, const void* src, bool valid) {
    asm volatile("cp.async.ca.shared.global [%0], [%1], 16, %2;\n"
                 :: "r"(smem_u32(dst)), "l"(src), "r"(valid ? 16 : 0));
}
__device__ __forceinline__ void cp_commit() { asm volatile("cp.async.commit_group;\n"); }
__device__ __forceinline__ void cp_wait0()  { asm volatile("cp.async.wait_group 0;\n"); }
__device__ __forceinline__ void cp_wait1()  { asm volatile("cp.async.wait_group 1;\n"); }
__device__ __forceinline__ void ldsm4(uint32_t* r, uint32_t a) {
    asm volatile("ldmatrix.sync.aligned.m8n8.x4.shared.b16 {%0,%1,%2,%3},[%4];"
                 : "=r"(r[0]), "=r"(r[1]), "=r"(r[2]), "=r"(r[3]) : "r"(a));
}
__device__ __forceinline__ void ldsm4t(uint32_t* r, uint32_t a) {
    asm volatile("ldmatrix.sync.aligned.m8n8.x4.trans.shared.b16 {%0,%1,%2,%3},[%4];"
                 : "=r"(r[0]), "=r"(r[1]), "=r"(r[2]), "=r"(r[3]) : "r"(a));
}
__device__ __forceinline__ void mma16816(float* c, const uint32_t* a, const uint32_t* b) {
    asm volatile("mma.sync.aligned.m16n8k16.row.col.f32.f16.f16.f32 "
                 "{%0,%1,%2,%3},{%4,%5,%6,%7},{%8,%9},{%0,%1,%2,%3};"
                 : "+f"(c[0]), "+f"(c[1]), "+f"(c[2]), "+f"(c[3])
                 : "r"(a[0]), "r"(a[1]), "r"(a[2]), "r"(a[3]), "r"(b[0]), "r"(b[1]));
}
__device__ __forceinline__ void split2(float v0, float v1, __half2& h2, __half2& l2) {
    __half h0 = __float2half_rn(v0), h1 = __float2half_rn(v1);
    __half l0 = __float2half_rn(v0 - __half2float(h0));
    __half l1 = __float2half_rn(v1 - __half2float(h1));
    h2 = __halves2half2(h0, h1);
    l2 = __halves2half2(l0, l1);
}
__device__ __forceinline__ uint32_t h2u(__half2 v) {
    uint32_t r; memcpy(&r, &v, 4); return r;
}

// ---------------- fp32 -> (hi[, lo]) fp16 split ----------------
__global__ void split_k(const float* __restrict__ s, __half* __restrict__ h,
                        __half* __restrict__ l, long long n4) {
    long long i = (long long)blockIdx.x * blockDim.x + threadIdx.x;
    if (i >= n4) return;
    float4 v = reinterpret_cast<const float4*>(s)[i];
    __half2 h0, l0, h1, l1;
    split2(v.x, v.y, h0, l0);
    split2(v.z, v.w, h1, l1);
    reinterpret_cast<__half2*>(h)[i * 2 + 0] = h0;
    reinterpret_cast<__half2*>(h)[i * 2 + 1] = h1;
    if (l) {
        reinterpret_cast<__half2*>(l)[i * 2 + 0] = l0;
        reinterpret_cast<__half2*>(l)[i * 2 + 1] = l1;
    }
}

// strided split: src[K][N] fp32 -> dst[K][ldd] (hi,lo) at col0; z = layer
__global__ void splits_k(const float* __restrict__ s, __half* __restrict__ dh,
                         __half* __restrict__ dl, int N, int ldd, int col0,
                         long long perz_src, long long perz_dst) {
    const float* sp = s + (long long)blockIdx.z * perz_src;
    __half* dhp = dh + (long long)blockIdx.z * perz_dst;
    __half* dlp = dl + (long long)blockIdx.z * perz_dst;
    long long i = (long long)blockIdx.x * blockDim.x + threadIdx.x;
    long long e = i * 4;
    if (e >= perz_src) return;
    int row = (int)(e / N), col = (int)(e % N);
    float4 v = *reinterpret_cast<const float4*>(sp + e);
    __half2 h0, l0, h1, l1;
    split2(v.x, v.y, h0, l0);
    split2(v.z, v.w, h1, l1);
    __half2* oh = reinterpret_cast<__half2*>(dhp + (long long)row * ldd + col0 + col);
    __half2* ol = reinterpret_cast<__half2*>(dlp + (long long)row * ldd + col0 + col);
    oh[0] = h0; oh[1] = h1;
    ol[0] = l0; ol[1] = l1;
}

// combined qkv bias
__global__ void catb_k(const float* __restrict__ bq, const float* __restrict__ bk,
                       const float* __restrict__ bv, float* __restrict__ dst) {
    int i = blockIdx.x * 256 + threadIdx.x;
    if (i >= NL * DMOD) return;
    int lyr = i / DMOD, d = i % DMOD;
    dst[lyr * 3072 + d]        = bq[i];
    dst[lyr * 3072 + 1024 + d] = bk[i];
    dst[lyr * 3072 + 2048 + d] = bv[i];
}

// ---------------- split-fp16 tensor-core GEMM (BM=128, BN=128, BK=32, 2-stage, 512 thr) ----------------
struct HP {
    const __half *Ah, *Al, *Bh, *Bl;
    float* Cf; __half *Chi, *Clo;
    const float* bias;
    int M, N, K, lda, ldb, ldc, bh;
    long long sA1, sA2, sB1, sB2, sC1, sC2, sBias1;
    const int* counts; const int* rowmap; int mapStride;
    const float* rowsc; float* scat; int scat_ld;
};

enum { EP_F32 = 0, EP_SPLIT = 1, EP_SPLIT_RELU = 2, EP_SCATTER = 3 };

// dyn smem (halves): Ahi[2][128][40] | Alo | Bhi[2][32][136] | Blo
#define H_ASTG  5120
#define H_ASL   10240
#define H_BSH   20480
#define H_BSTG  4352
#define H_BSL   29184
#define HSMEM_BYTES (37888 * 2) // 75776 B

// NTERM: 3 = ah*bh + al*bh + ah*bl ; 2 = ah*bh + al*bh ; 1 = ah*bh
// 512 threads: 16 warps in 4x4 grid, warp tile 32x32 (MM=2, MN=4) — low reg
// pressure so the whole CTA fits one SM with 16 resident warps (4/SMSP).
template<bool GATHER, int MODE, int NTERM>
__global__ __launch_bounds__(512) void hgemm_k(HP p) {
    constexpr int BM = 128, BN = 128, BK = 32;
    constexpr int WCOLS = 4;
    constexpr int WM = 32, WN = 32, MM = 2, MN = 4;
    constexpr int APAD = 40, BPAD = 136;
    extern __shared__ __half sm[];

    const int z  = blockIdx.z;
    const int b2 = z / p.bh, b1 = z % p.bh;
    const __half* Ah = p.Ah + b2 * p.sA2 + b1 * p.sA1;
    const __half* Al = (NTERM >= 2) ? p.Al + b2 * p.sA2 + b1 * p.sA1 : nullptr;
    const __half* Bh = p.Bh + b2 * p.sB2 + b1 * p.sB1;
    const __half* Bl = (NTERM == 3) ? p.Bl + b2 * p.sB2 + b1 * p.sB1 : nullptr;
    const int M = p.counts ? p.counts[z] : p.M;
    const int row0 = blockIdx.y * BM;
    if (row0 >= M) return;
    const int col0 = blockIdx.x * BN;

    const int tid = threadIdx.x;
    const int l   = tid & 31;
    const int wid = tid >> 5;          // 0..15
    const int wr  = wid >> 2, wc = wid & 3;

    const int* rmap = (GATHER || MODE == EP_SCATTER)
                      ? p.rowmap + (long long)z * p.mapStride : nullptr;

    float acc[MM][MN][4];
#pragma unroll
    for (int i = 0; i < MM; i++)
#pragma unroll
        for (int j = 0; j < MN; j++)
#pragma unroll
            for (int r = 0; r < 4; r++) acc[i][j][r] = 0.f;

    // A loader: 512 chunks per array -> exactly 1 per thread
    const int aRow = tid >> 2, aK0 = (tid & 3) * 8;
    const bool av = (row0 + aRow) < M;
    long long aB;
    if (GATHER) {
        aB = (long long)(av ? rmap[row0 + aRow] : 0) * p.lda;
    } else {
        aB = (long long)(row0 + aRow) * p.lda;
    }
    // B loader: 512 chunks per array -> 1 per thread
    const int bRow = tid >> 4, bN0 = (tid & 15) * 8;

    auto loadA = [&](int kt, int st) {
        const int k0 = kt * BK;
        __half* Asth = sm + st * H_ASTG;
        cp16(Asth + aRow * APAD + aK0, Ah + aB + k0 + aK0, av);
        if (NTERM >= 2) {
            __half* Astl = sm + H_ASL + st * H_ASTG;
            cp16(Astl + aRow * APAD + aK0, Al + aB + k0 + aK0, av);
        }
    };
    auto loadB = [&](int kt, int st) {
        const int k0 = kt * BK;
        __half* Bsth = sm + H_BSH + st * H_BSTG;
        cp16(Bsth + bRow * BPAD + bN0, Bh + (long long)(k0 + bRow) * p.ldb + col0 + bN0, true);
        if (NTERM == 3) {
            __half* Bstl = sm + H_BSL + st * H_BSTG;
            cp16(Bstl + bRow * BPAD + bN0, Bl + (long long)(k0 + bRow) * p.ldb + col0 + bN0, true);
        }
    };

    auto compute = [&](int st) {
        __half* Asth = sm + st * H_ASTG;
        __half* Astl = sm + H_ASL + st * H_ASTG;
        __half* Bsth = sm + H_BSH + st * H_BSTG;
        __half* Bstl = sm + H_BSL + st * H_BSTG;
#pragma unroll
        for (int ks = 0; ks < 2; ks++) {
            uint32_t fah[MM][4], fal[MM][4], fbh[MN][2], fbl[MN][2];
#pragma unroll
            for (int mi = 0; mi < MM; mi++) {
                const int r = wr * WM + mi * 16 + (l & 15);
                const int c = ks * 16 + ((l >> 4) << 3);
                ldsm4(fah[mi], smem_u32(Asth + r * APAD + c));
                if (NTERM >= 2) ldsm4(fal[mi], smem_u32(Astl + r * APAD + c));
            }
#pragma unroll
            for (int nj = 0; nj < MN / 2; nj++) {
                const int r = ks * 16 + (l & 15);
                const int c = wc * WN + nj * 16 + ((l >> 4) << 3);
                uint32_t r4[4];
                ldsm4t(r4, smem_u32(Bsth + r * BPAD + c));
                fbh[2*nj][0] = r4[0]; fbh[2*nj][1] = r4[1];
                fbh[2*nj+1][0] = r4[2]; fbh[2*nj+1][1] = r4[3];
                if (NTERM == 3) {
                    ldsm4t(r4, smem_u32(Bstl + r * BPAD + c));
                    fbl[2*nj][0] = r4[0]; fbl[2*nj][1] = r4[1];
                    fbl[2*nj+1][0] = r4[2]; fbl[2*nj+1][1] = r4[3];
                }
            }
#pragma unroll
            for (int mi = 0; mi < MM; mi++)
#pragma unroll
                for (int ni = 0; ni < MN; ni++) {
                    mma16816(acc[mi][ni], fah[mi], fbh[ni]);
                    if (NTERM >= 2) mma16816(acc[mi][ni], fal[mi], fbh[ni]);
                    if (NTERM == 3) mma16816(acc[mi][ni], fah[mi], fbl[ni]);
                }
        }
    };

    const int nK = p.K / BK;
    loadA(0, 0); loadB(0, 0); cp_commit();
    for (int kt = 0; kt < nK; kt++) {
        const int st = kt & 1;
        if (kt + 1 < nK) {
            loadA(kt + 1, st ^ 1); loadB(kt + 1, st ^ 1); cp_commit();
            cp_wait1();
        } else {
            cp_wait0();
        }
        __syncthreads();
        compute(st);
        __syncthreads();
    }

    const float* bias = p.bias ? p.bias + b1 * p.sBias1 : nullptr;
    float*  Cf  = p.Cf  ? p.Cf  + b2 * p.sC2 + b1 * p.sC1 : nullptr;
    __half* Chi = p.Chi ? p.Chi + b2 * p.sC2 + b1 * p.sC1 : nullptr;
    __half* Clo = p.Clo ? p.Clo + b2 * p.sC2 + b1 * p.sC1 : nullptr;
#pragma unroll
    for (int mi = 0; mi < MM; mi++) {
#pragma unroll
        for (int hh = 0; hh < 2; hh++) {
            const int r = row0 + wr * WM + mi * 16 + (l >> 2) + hh * 8;
            if (r >= M) continue;
#pragma unroll
            for (int ni = 0; ni < MN; ni++) {
                const int c = col0 + wc * WN + ni * 8 + (l & 3) * 2;
                float v0 = acc[mi][ni][hh * 2 + 0];
                float v1 = acc[mi][ni][hh * 2 + 1];
                if (bias) { v0 += bias[c]; v1 += bias[c + 1]; }
                if (MODE == EP_SPLIT_RELU) { v0 = fmaxf(v0, 0.f); v1 = fmaxf(v1, 0.f); }
                if (MODE == EP_SCATTER) {
                    const int tok = rmap[r];
                    const float w = p.rowsc[(long long)z * p.mapStride + r];
                    atomicAdd(p.scat + (long long)tok * p.scat_ld + c,     w * v0);
                    atomicAdd(p.scat + (long long)tok * p.scat_ld + c + 1, w * v1);
                } else if (MODE == EP_F32) {
                    *reinterpret_cast<float2*>(Cf + (long long)r * p.ldc + c) =
                        make_float2(v0, v1);
                } else {
                    __half2 h2, l2;
                    split2(v0, v1, h2, l2);
                    *reinterpret_cast<__half2*>(Chi + (long long)r * p.ldc + c) = h2;
                    *reinterpret_cast<__half2*>(Clo + (long long)r * p.ldc + c) = l2;
                }
            }
        }
    }
}

// ---------------- fused flash attention ----------------
#define FA_SMEM 108544
__global__ __launch_bounds__(256) void fa_k(const __half* __restrict__ qkvh,
                                            const __half* __restrict__ qkvl,
                                            __half* __restrict__ aoh,
                                            __half* __restrict__ aol) {
    extern __shared__ __align__(16) __half fs[];
    __half* Qh  = fs;            // [128][72]
    __half* Ql  = fs + 9216;
    __half* Kth = fs + 18432;    // [64][136] transposed K chunk
    __half* Ktl = fs + 27136;
    __half* Vh  = fs + 35840;    // [128][72] V chunk
    __half* Vl  = fs + 45056;
    const int z = blockIdx.z, b = z / NH, h = z % NH;
    const int q0 = blockIdx.y * 128;
    const int tid = threadIdx.x, l = tid & 31, w = tid >> 5;

#pragma unroll
    for (int i = 0; i < 4; i++) {
        int c = tid + i * 256;
        int row = c >> 3, k8 = (c & 7) * 8;
        long long g = ((long long)(b * SEQ + q0 + row)) * 3072 + h * 64 + k8;
        cp16(Qh + row * 72 + k8, qkvh + g, true);
        cp16(Ql + row * 72 + k8, qkvl + g, true);
    }
    cp_commit();

    float accO[8][4];
#pragma unroll
    for (int i = 0; i < 8; i++)
#pragma unroll
        for (int j = 0; j < 4; j++) accO[i][j] = 0.f;
    float m0 = -1e30f, m1 = -1e30f, s0 = 0.f, s1 = 0.f;

    uint32_t qah[4][4], qal[4][4];

    for (int c = 0; c < 8; c++) {
        const int k0r = c * 128;
        __syncthreads();
#pragma unroll
        for (int i = 0; i < 4; i++) {
            int cc = tid + i * 256;
            int n = cc >> 3, k8 = (cc & 7) * 8;
            long long gk = ((long long)(b * SEQ + k0r + n)) * 3072 + 1024 + h * 64 + k8;
            uint4 rh = *reinterpret_cast<const uint4*>(qkvh + gk);
            uint4 rl = *reinterpret_cast<const uint4*>(qkvl + gk);
            __half hh[8], ll[8];
            memcpy(hh, &rh, 16); memcpy(ll, &rl, 16);
#pragma unroll
            for (int j = 0; j < 8; j++) {
                Kth[(k8 + j) * 136 + n] = hh[j];
                Ktl[(k8 + j) * 136 + n] = ll[j];
            }
            long long gv = ((long long)(b * SEQ + k0r + n)) * 3072 + 2048 + h * 64 + k8;
            cp16(Vh + n * 72 + k8, qkvh + gv, true);
            cp16(Vl + n * 72 + k8, qkvl + gv, true);
        }
        cp_commit();
        cp_wait0();
        __syncthreads();
        if (c == 0) {
#pragma unroll
            for (int ks = 0; ks < 4; ks++) {
                const int r = w * 16 + (l & 15);
                const int cq = ks * 16 + ((l >> 4) << 3);
                ldsm4(qah[ks], smem_u32(Qh + r * 72 + cq));
                ldsm4(qal[ks], smem_u32(Ql + r * 72 + cq));
            }
        }
        float sacc[16][4];
#pragma unroll
        for (int t = 0; t < 16; t++)
#pragma unroll
            for (int j = 0; j < 4; j++) sacc[t][j] = 0.f;
#pragma unroll
        for (int ks = 0; ks < 4; ks++) {
#pragma unroll
            for (int nj = 0; nj < 8; nj++) {
                const int r = ks * 16 + (l & 15);
                const int cc2 = nj * 16 + ((l >> 4) << 3);
                uint32_t r4h[4], r4l[4];
                ldsm4t(r4h, smem_u32(Kth + r * 136 + cc2));
                ldsm4t(r4l, smem_u32(Ktl + r * 136 + cc2));
                uint32_t bh0[2] = {r4h[0], r4h[1]}, bh1[2] = {r4h[2], r4h[3]};
                uint32_t bl0[2] = {r4l[0], r4l[1]}, bl1[2] = {r4l[2], r4l[3]};
                mma16816(sacc[2*nj],   qah[ks], bh0);
                mma16816(sacc[2*nj],   qal[ks], bh0);
                mma16816(sacc[2*nj],   qah[ks], bl0);
                mma16816(sacc[2*nj+1], qah[ks], bh1);
                mma16816(sacc[2*nj+1], qal[ks], bh1);
                mma16816(sacc[2*nj+1], qah[ks], bl1);
            }
        }
        const float scale = 0.125f;
        float nm0 = m0, nm1 = m1;
#pragma unroll
        for (int t = 0; t < 16; t++) {
            sacc[t][0] *= scale; sacc[t][1] *= scale;
            sacc[t][2] *= scale; sacc[t][3] *= scale;
            nm0 = fmaxf(nm0, fmaxf(sacc[t][0], sacc[t][1]));
            nm1 = fmaxf(nm1, fmaxf(sacc[t][2], sacc[t][3]));
        }
        nm0 = fmaxf(nm0, __shfl_xor_sync(0xffffffffu, nm0, 1));
        nm0 = fmaxf(nm0, __shfl_xor_sync(0xffffffffu, nm0, 2));
        nm1 = fmaxf(nm1, __shfl_xor_sync(0xffffffffu, nm1, 1));
        nm1 = fmaxf(nm1, __shfl_xor_sync(0xffffffffu, nm1, 2));
        const float al0 = __expf(m0 - nm0), al1 = __expf(m1 - nm1);
        m0 = nm0; m1 = nm1;
        float ls0 = 0.f, ls1 = 0.f;
#pragma unroll
        for (int t = 0; t < 16; t++) {
            sacc[t][0] = __expf(sacc[t][0] - m0);
            sacc[t][1] = __expf(sacc[t][1] - m0);
            sacc[t][2] = __expf(sacc[t][2] - m1);
            sacc[t][3] = __expf(sacc[t][3] - m1);
            ls0 += sacc[t][0] + sacc[t][1];
            ls1 += sacc[t][2] + sacc[t][3];
        }
        ls0 += __shfl_xor_sync(0xffffffffu, ls0, 1);
        ls0 += __shfl_xor_sync(0xffffffffu, ls0, 2);
        ls1 += __shfl_xor_sync(0xffffffffu, ls1, 1);
        ls1 += __shfl_xor_sync(0xffffffffu, ls1, 2);
        s0 = s0 * al0 + ls0;
        s1 = s1 * al1 + ls1;
#pragma unroll
        for (int t8 = 0; t8 < 8; t8++) {
            accO[t8][0] *= al0; accO[t8][1] *= al0;
            accO[t8][2] *= al1; accO[t8][3] *= al1;
        }
#pragma unroll
        for (int j = 0; j < 8; j++) {
            __half2 ph0, pl0, ph1, pl1, ph2, pl2, ph3, pl3;
            split2(sacc[2*j][0],   sacc[2*j][1],   ph0, pl0);
            split2(sacc[2*j][2],   sacc[2*j][3],   ph1, pl1);
            split2(sacc[2*j+1][0], sacc[2*j+1][1], ph2, pl2);
            split2(sacc[2*j+1][2], sacc[2*j+1][3], ph3, pl3);
            uint32_t pah[4] = {h2u(ph0), h2u(ph1), h2u(ph2), h2u(ph3)};
            uint32_t pal[4] = {h2u(pl0), h2u(pl1), h2u(pl2), h2u(pl3)};
#pragma unroll
            for (int vn = 0; vn < 4; vn++) {
                const int r = j * 16 + (l & 15);
                const int cv = vn * 16 + ((l >> 4) << 3);
                uint32_t r4h[4], r4l[4];
                ldsm4t(r4h, smem_u32(Vh + r * 72 + cv));
                ldsm4t(r4l, smem_u32(Vl + r * 72 + cv));
                uint32_t bh0[2] = {r4h[0], r4h[1]}, bh1[2] = {r4h[2], r4h[3]};
                uint32_t bl0[2] = {r4l[0], r4l[1]}, bl1[2] = {r4l[2], r4l[3]};
                mma16816(accO[2*vn],   pah, bh0);
                mma16816(accO[2*vn],   pal, bh0);
                mma16816(accO[2*vn],   pah, bl0);
                mma16816(accO[2*vn+1], pah, bh1);
                mma16816(accO[2*vn+1], pal, bh1);
                mma16816(accO[2*vn+1], pah, bl1);
            }
        }
    }
    const float inv0 = 1.f / s0, inv1 = 1.f / s1;
    const int r0 = q0 + w * 16 + (l >> 2);
    const int r1 = r0 + 8;
    const long long t0g = (long long)(b * SEQ + r0) * DMOD + h * 64;
    const long long t1g = (long long)(b * SEQ + r1) * DMOD + h * 64;
#pragma unroll
    for (int t8 = 0; t8 < 8; t8++) {
        const int cdim = t8 * 8 + (l & 3) * 2;
        __half2 hh, llh;
        split2(accO[t8][0] * inv0, accO[t8][1] * inv0, hh, llh);
        *reinterpret_cast<__half2*>(aoh + t0g + cdim) = hh;
        *reinterpret_cast<__half2*>(aol + t0g + cdim) = llh;
        split2(accO[t8][2] * inv1, accO[t8][3] * inv1, hh, llh);
        *reinterpret_cast<__half2*>(aoh + t1g + cdim) = hh;
        *reinterpret_cast<__half2*>(aol + t1g + cdim) = llh;
    }
}

// ---------------- embedding + positional encoding ----------------
__global__ void embed_k(const int* __restrict__ src, const float* __restrict__ emb,
                        float* __restrict__ xf, __half* __restrict__ xh,
                        __half* __restrict__ xl) {
    const int t = blockIdx.x;
    const int s = t % SEQ;
    const int tok = src[t];
    const float c = -logf(10000.0f) / (float)DMOD;
    for (int d = threadIdx.x; d < DMOD; d += blockDim.x) {
        const int i = d >> 1;
        const float div = expf((float)(2 * i) * c);
        const float ang = (float)s * div;
        const float pe = (d & 1) ? cosf(ang) : sinf(ang);
        const float v = emb[(long long)tok * DMOD + d] * 32.0f + pe;
        xf[(long long)t * DMOD + d] = v;
        __half h = __float2half_rn(v);
        xh[(long long)t * DMOD + d] = h;
        xl[(long long)t * DMOD + d] = __float2half_rn(v - __half2float(h));
    }
}

// ---------------- layernorm ----------------
__global__ void ln_k(const float* __restrict__ a, const float* __restrict__ res,
                     const float* __restrict__ g, const float* __restrict__ be,
                     float* __restrict__ of, __half* __restrict__ oh,
                     __half* __restrict__ ol) {
    const int row = blockIdx.x;
    const int tid = threadIdx.x;
    float4 v = reinterpret_cast<const float4*>(a + (long long)row * DMOD)[tid];
    if (res) {
        float4 r = reinterpret_cast<const float4*>(res + (long long)row * DMOD)[tid];
        v.x += r.x; v.y += r.y; v.z += r.z; v.w += r.w;
    }
    float s  = v.x + v.y + v.z + v.w;
    float sq = v.x*v.x + v.y*v.y + v.z*v.z + v.w*v.w;
    __shared__ float rs[8], rq[8];
    for (int o = 16; o > 0; o >>= 1) {
        s  += __shfl_xor_sync(0xffffffffu, s,  o);
        sq += __shfl_xor_sync(0xffffffffu, sq, o);
    }
    if ((tid & 31) == 0) { rs[tid >> 5] = s; rq[tid >> 5] = sq; }
    __syncthreads();
    __shared__ float s_mu, s_inv;
    if (tid == 0) {
        float S = 0.f, Q = 0.f;
        for (int i = 0; i < 8; i++) { S += rs[i]; Q += rq[i]; }
        const float mu  = S / (float)DMOD;
        const float var = Q / (float)DMOD - mu * mu;
        s_mu = mu; s_inv = rsqrtf(var + 1e-5f);
    }
    __syncthreads();
    const float mu = s_mu, inv = s_inv;
    const float4 gv = reinterpret_cast<const float4*>(g)[tid];
    const float4 bv = reinterpret_cast<const float4*>(be)[tid];
    float o0 = (v.x - mu) * inv * gv.x + bv.x;
    float o1 = (v.y - mu) * inv * gv.y + bv.y;
    float o2 = (v.z - mu) * inv * gv.z + bv.z;
    float o3 = (v.w - mu) * inv * gv.w + bv.w;
    if (of) reinterpret_cast<float4*>(of + (long long)row * DMOD)[tid] = make_float4(o0, o1, o2, o3);
    __half2 h0, l0, h1, l1;
    split2(o0, o1, h0, l0);
    split2(o2, o3, h1, l1);
    reinterpret_cast<__half2*>(oh + (long long)row * DMOD)[tid * 2 + 0] = h0;
    reinterpret_cast<__half2*>(oh + (long long)row * DMOD)[tid * 2 + 1] = h1;
    reinterpret_cast<__half2*>(ol + (long long)row * DMOD)[tid * 2 + 0] = l0;
    reinterpret_cast<__half2*>(ol + (long long)row * DMOD)[tid * 2 + 1] = l1;
}

// ---------------- zero moe accumulator + counters ----------------
__global__ void zero_k(float* __restrict__ moe, int* __restrict__ cnt) {
    long long i = (long long)blockIdx.x * blockDim.x + threadIdx.x;
    const long long n = (long long)TTOK * DMOD;
    for (; i < n; i += (long long)gridDim.x * blockDim.x) moe[i] = 0.f;
    if (blockIdx.x == 0 && threadIdx.x < NE) cnt[threadIdx.x] = 0;
}

// ---------------- gate ----------------
__global__ void gate_k(const float* __restrict__ x, const float* __restrict__ gw,
                       const float* __restrict__ gb, int* __restrict__ cnt,
                       int* __restrict__ perm, float* __restrict__ pw) {
    const int t = blockIdx.x;
    const int tid = threadIdx.x;
    float acc[NE];
#pragma unroll
    for (int e = 0; e < NE; e++) acc[e] = 0.f;
    for (int d = tid; d < DMOD; d += 256) {
        const float xv = x[(long long)t * DMOD + d];
        const float* grow = gw + (long long)d * NE;
#pragma unroll
        for (int e = 0; e < NE; e++) acc[e] += xv * grow[e];
    }
    __shared__ float sh[NE][8];
    const int lane = tid & 31, wid = tid >> 5;
#pragma unroll
    for (int e = 0; e < NE; e++) {
        float s = acc[e];
        for (int o = 16; o > 0; o >>= 1) s += __shfl_xor_sync(0xffffffffu, s, o);
        if (lane == 0) sh[e][wid] = s;
    }
    __syncthreads();
    if (tid == 0) {
        float lg[NE];
#pragma unroll
        for (int e = 0; e < NE; e++) {
            float s = 0.f;
            for (int w = 0; w < 8; w++) s += sh[e][w];
            lg[e] = s + gb[e];
        }
        int i0 = 0;
        for (int e = 1; e < NE; e++) if (lg[e] > lg[i0]) i0 = e;
        int i1 = (i0 == 0) ? 1 : 0;
        for (int e = 0; e < NE; e++) if (e != i0 && lg[e] > lg[i1]) i1 = e;
        const float e1 = expf(lg[i1] - lg[i0]);
        const float inv = 1.0f / (1.0f + e1);
        int p0 = atomicAdd(&cnt[i0], 1); perm[i0 * TTOK + p0] = t; pw[i0 * TTOK + p0] = inv;
        int p1 = atomicAdd(&cnt[i1], 1); perm[i1 * TTOK + p1] = t; pw[i1 * TTOK + p1] = e1 * inv;
    }
}

// ---------------- host orchestration ----------------
static inline void splitw(const float* s, __half* h, __half* l, long long n) {
    long long n4 = n / 4;
    split_k<<<(unsigned)((n4 + 255) / 256), 256>>>(s, h, l, n4);
}

extern "C" void kernel_launch(void* const* d_in, const int* in_sizes, int n_in,
                              void* d_out, int out_size) {
    (void)in_sizes; (void)n_in; (void)out_size;
    const int*   src    = (const int*)  d_in[0];
    const float* emb    = (const float*)d_in[1];
    const float* Wq     = (const float*)d_in[2];
    const float* bq     = (const float*)d_in[3];
    const float* Wk     = (const float*)d_in[4];
    const float* bk     = (const float*)d_in[5];
    const float* Wv     = (const float*)d_in[6];
    const float* bv     = (const float*)d_in[7];
    const float* Wo     = (const float*)d_in[8];
    const float* bo     = (const float*)d_in[9];
    const float* ln1_g  = (const float*)d_in[10];
    const float* ln1_b  = (const float*)d_in[11];
    const float* W1     = (const float*)d_in[12];
    const float* b1     = (const float*)d_in[13];
    const float* W2     = (const float*)d_in[14];
    const float* b2     = (const float*)d_in[15];
    const float* ln2_g  = (const float*)d_in[16];
    const float* ln2_b  = (const float*)d_in[17];
    const float* gate_W = (const float*)d_in[18];
    const float* gate_b = (const float*)d_in[19];
    const float* eW1    = (const float*)d_in[20];
    const float* eb1    = (const float*)d_in[21];
    const float* eW2    = (const float*)d_in[22];
    const float* eb2    = (const float*)d_in[23];
    const float* fln_g  = (const float*)d_in[24];
    const float* fln_b  = (const float*)d_in[25];
    const float* out_W  = (const float*)d_in[26];
    const float* out_b  = (const float*)d_in[27];

#define SYM(v, s) cudaGetSymbolAddress((void**)&v, s)
    __half *qkvw_h,*qkvw_l,*wo_h,*wo_l,*w1_h,*w1_l,*w2_h,*w2_l,*ew1_h,*ew2_h,*ow_h;
    __half *x_h,*x_l,*qkv_h,*qkv_l,*ao_h,*ao_l;
    __half *ffh_h,*ffh_l,*mh_h,*mh_l,*xn_h,*xn_l;
    float *bqkv,*xf,*t1f,*moef,*xnf,*pw;
    int *cnt,*perm;
    SYM(qkvw_h,g_qkvw_h); SYM(qkvw_l,g_qkvw_l); SYM(bqkv,g_bqkv);
    SYM(wo_h,g_wo_h); SYM(wo_l,g_wo_l);
    SYM(w1_h,g_w1_h); SYM(w1_l,g_w1_l); SYM(w2_h,g_w2_h); SYM(w2_l,g_w2_l);
    SYM(ew1_h,g_ew1_h); SYM(ew2_h,g_ew2_h); SYM(ow_h,g_ow_h);
    SYM(x_h,g_x_h); SYM(x_l,g_x_l); SYM(qkv_h,g_qkv_h); SYM(qkv_l,g_qkv_l);
    SYM(ao_h,g_ao_h); SYM(ao_l,g_ao_l);
    SYM(ffh_h,g_ffh_h); SYM(ffh_l,g_ffh_l); SYM(mh_h,g_mh_h); SYM(mh_l,g_mh_l);
    SYM(xn_h,g_xn_h); SYM(xn_l,g_xn_l);
    SYM(xf,g_xf); SYM(t1f,g_t1f); SYM(moef,g_moef); SYM(xnf,g_xnf);
    SYM(pw,g_pw); SYM(cnt,g_cnt); SYM(perm,g_perm);
#undef SYM

    cudaFuncSetAttribute(fa_k, cudaFuncAttributeMaxDynamicSharedMemorySize, FA_SMEM);
    cudaFuncSetAttribute(hgemm_k<false,EP_SPLIT,3>,      cudaFuncAttributeMaxDynamicSharedMemorySize, HSMEM_BYTES);
    cudaFuncSetAttribute(hgemm_k<false,EP_F32,3>,        cudaFuncAttributeMaxDynamicSharedMemorySize, HSMEM_BYTES);
    cudaFuncSetAttribute(hgemm_k<false,EP_SPLIT_RELU,3>, cudaFuncAttributeMaxDynamicSharedMemorySize, HSMEM_BYTES);
    cudaFuncSetAttribute(hgemm_k<true, EP_SPLIT_RELU,1>, cudaFuncAttributeMaxDynamicSharedMemorySize, HSMEM_BYTES);
    cudaFuncSetAttribute(hgemm_k<false,EP_SCATTER,1>,    cudaFuncAttributeMaxDynamicSharedMemorySize, HSMEM_BYTES);
    cudaFuncSetAttribute(hgemm_k<false,EP_F32,1>,        cudaFuncAttributeMaxDynamicSharedMemorySize, HSMEM_BYTES);

    {
        long long perz = (long long)DMOD * DMOD;
        unsigned blks = (unsigned)((perz / 4 + 255) / 256);
        splits_k<<<dim3(blks,1,NL),256>>>(Wq, qkvw_h, qkvw_l, DMOD, 3072, 0,    perz, (long long)DMOD*3072);
        splits_k<<<dim3(blks,1,NL),256>>>(Wk, qkvw_h, qkvw_l, DMOD, 3072, 1024, perz, (long long)DMOD*3072);
        splits_k<<<dim3(blks,1,NL),256>>>(Wv, qkvw_h, qkvw_l, DMOD, 3072, 2048, perz, (long long)DMOD*3072);
        catb_k<<<(NL*DMOD + 255)/256, 256>>>(bq, bk, bv, bqkv);
    }
    splitw(Wo,  wo_h,  wo_l,  (long long)NL * DMOD * DMOD);
    splitw(W1,  w1_h,  w1_l,  (long long)NL * DMOD * FDIM);
    splitw(W2,  w2_h,  w2_l,  (long long)NL * FDIM * DMOD);
    splitw(eW1, ew1_h, nullptr, (long long)NE * DMOD * FDIM);
    splitw(eW2, ew2_h, nullptr, (long long)NE * FDIM * DMOD);
    splitw(out_W, ow_h, nullptr, (long long)DMOD * VOC);

    embed_k<<<TTOK, 256>>>(src, emb, xf, x_h, x_l);

    for (int l = 0; l < NL; l++) {
        HP p;
        // fused QKV: x @ Wqkv (N=3072)
        p = HP{};
        p.Ah = x_h; p.Al = x_l;
        p.Bh = qkvw_h + (long long)l*DMOD*3072; p.Bl = qkvw_l + (long long)l*DMOD*3072;
        p.Chi = qkv_h; p.Clo = qkv_l; p.bias = bqkv + l*3072;
        p.M = TTOK; p.N = 3072; p.K = DMOD;
        p.lda = DMOD; p.ldb = 3072; p.ldc = 3072; p.bh = 1;
        hgemm_k<false,EP_SPLIT,3><<<dim3(24,16,1),512,HSMEM_BYTES>>>(p);
        // fused flash attention -> ao (split)
        fa_k<<<dim3(1,8,NBAT*NH),256,FA_SMEM>>>(qkv_h, qkv_l, ao_h, ao_l);
        // ao @ Wo + bo
        p = HP{};
        p.Ah = ao_h; p.Al = ao_l;
        p.Bh = wo_h + (long long)l*DMOD*DMOD; p.Bl = wo_l + (long long)l*DMOD*DMOD;
        p.Cf = t1f; p.bias = bo + l*DMOD;
        p.M = TTOK; p.N = DMOD; p.K = DMOD;
        p.lda = DMOD; p.ldb = DMOD; p.ldc = DMOD; p.bh = 1;
        hgemm_k<false,EP_F32,3><<<dim3(8,16,1),512,HSMEM_BYTES>>>(p);
        ln_k<<<TTOK, 256>>>(t1f, xf, ln1_g + l*DMOD, ln1_b + l*DMOD, xf, x_h, x_l);
        // ffh = relu(x @ W1 + b1)
        p = HP{};
        p.Ah = x_h; p.Al = x_l;
        p.Bh = w1_h + (long long)l*DMOD*FDIM; p.Bl = w1_l + (long long)l*DMOD*FDIM;
        p.Chi = ffh_h; p.Clo = ffh_l; p.bias = b1 + l*FDIM;
        p.M = TTOK; p.N = FDIM; p.K = DMOD;
        p.lda = DMOD; p.ldb = FDIM; p.ldc = FDIM; p.bh = 1;
        hgemm_k<false,EP_SPLIT_RELU,3><<<dim3(32,16,1),512,HSMEM_BYTES>>>(p);
        // ff = ffh @ W2 + b2
        p = HP{};
        p.Ah = ffh_h; p.Al = ffh_l;
        p.Bh = w2_h + (long long)l*FDIM*DMOD; p.Bl = w2_l + (long long)l*FDIM*DMOD;
        p.Cf = t1f; p.bias = b2 + l*DMOD;
        p.M = TTOK; p.N = DMOD; p.K = FDIM;
        p.lda = FDIM; p.ldb = DMOD; p.ldc = DMOD; p.bh = 1;
        hgemm_k<false,EP_F32,3><<<dim3(8,16,1),512,HSMEM_BYTES>>>(p);
        ln_k<<<TTOK, 256>>>(t1f, xf, ln2_g + l*DMOD, ln2_b + l*DMOD, xf, x_h, x_l);
    }

    // MoE (post-gate: NTERM=1 hi-only experts)
    zero_k<<<2048, 256>>>(moef, cnt);
    gate_k<<<TTOK, 256>>>(xf, gate_W, gate_b, cnt, perm, pw);
    {
        HP p = HP{};
        p.Ah = x_h; p.Bh = ew1_h;
        p.Chi = mh_h; p.Clo = mh_l; p.bias = eb1;
        p.M = TTOK; p.N = FDIM; p.K = DMOD;
        p.lda = DMOD; p.ldb = FDIM; p.ldc = FDIM; p.bh = NE;
        p.sB1 = (long long)DMOD * FDIM; p.sC1 = (long long)TTOK * FDIM; p.sBias1 = FDIM;
        p.counts = cnt; p.rowmap = perm; p.mapStride = TTOK;
        hgemm_k<true,EP_SPLIT_RELU,1><<<dim3(32,16,NE),512,HSMEM_BYTES>>>(p);
    }
    {
        HP p = HP{};
        p.Ah = mh_h; p.Bh = ew2_h; p.bias = eb2;
        p.M = TTOK; p.N = DMOD; p.K = FDIM;
        p.lda = FDIM; p.ldb = DMOD; p.bh = NE;
        p.sA1 = (long long)TTOK * FDIM; p.sB1 = (long long)FDIM * DMOD; p.sBias1 = DMOD;
        p.counts = cnt; p.rowmap = perm; p.mapStride = TTOK;
        p.rowsc = pw; p.scat = moef; p.scat_ld = DMOD;
        hgemm_k<false,EP_SCATTER,1><<<dim3(8,16,NE),512,HSMEM_BYTES>>>(p);
    }
    ln_k<<<TTOK, 256>>>(moef, nullptr, fln_g, fln_b, xnf, xn_h, xn_l);
    // output projection -> d_out (hi-only NTERM=1)
    {
        HP p = HP{};
        p.Ah = xn_h; p.Bh = ow_h;
        p.Cf = (float*)d_out; p.bias = out_b;
        p.M = TTOK; p.N = VOC; p.K = DMOD;
        p.lda = DMOD; p.ldb = VOC; p.ldc = VOC; p.bh = 1;
        hgemm_k<false,EP_F32,1><<<dim3(250,16,1),512,HSMEM_BYTES>>>(p);
    }
}

// round 15
// speedup vs baseline: 1.0488x; 1.0488x over previous
#include <cuda_runtime.h>
#include <cuda_fp16.h>
#include <math.h>
#include <stdint.h>
#include <string.h>

#define TTOK 2048
#define DMOD 1024
#define FDIM 4096
#define SEQ  1024
#define NBAT 2
#define NH   16
#define HDM  64
#define NE   8
#define VOC  32000
#define NL   3

// ---------------- scratch (static device globals; no allocation) ----------------
__device__ __half g_qkvw_h[NL*DMOD*3072], g_qkvw_l[NL*DMOD*3072];
__device__ float  g_bqkv  [NL*3072];
__device__ __half g_wo_h [NL*DMOD*DMOD], g_wo_l [NL*DMOD*DMOD];
__device__ __half g_w1_h [NL*DMOD*FDIM], g_w1_l [NL*DMOD*FDIM];
__device__ __half g_w2_h [NL*FDIM*DMOD], g_w2_l [NL*FDIM*DMOD];
__device__ __half g_ew1_h[NE*DMOD*FDIM];
__device__ __half g_ew2_h[NE*FDIM*DMOD];
__device__ __half g_ow_h [DMOD*VOC];
// activations split hi/lo
__device__ __half g_x_h  [TTOK*DMOD], g_x_l  [TTOK*DMOD];
__device__ __half g_qkv_h[TTOK*3072], g_qkv_l[TTOK*3072];
__device__ __half g_ao_h [TTOK*DMOD], g_ao_l [TTOK*DMOD];
__device__ __half g_ffh_h[TTOK*FDIM], g_ffh_l[TTOK*FDIM];
__device__ __half g_mh_h [NE*TTOK*FDIM], g_mh_l [NE*TTOK*FDIM];
__device__ __half g_xn_h [TTOK*DMOD], g_xn_l [TTOK*DMOD];
// fp32 intermediates
__device__ float  g_xf  [TTOK*DMOD];
__device__ float  g_t1f [TTOK*DMOD];
__device__ float  g_moef[TTOK*DMOD];
__device__ float  g_xnf [TTOK*DMOD];
__device__ int    g_cnt [NE];
__device__ int    g_perm[NE*TTOK];
__device__ float  g_pw  [NE*TTOK];

// ---------------- PTX helpers ----------------
__device__ __forceinline__ uint32_t smem_u32(const void* p) {
    return (uint32_t)__cvta_generic_to_shared(p);
}
__device__ __forceinline__ void cp16(void* dst, const void* src, bool valid) {
    asm volatile("cp.async.ca.shared.global [%0], [%1], 16, %2;\n"
                 :: "r"(smem_u32(dst)), "l"(src), "r"(valid ? 16 : 0));
}
__device__ __forceinline__ void cp_commit() { asm volatile("cp.async.commit_group;\n"); }
__device__ __forceinline__ void cp_wait0()  { asm volatile("cp.async.wait_group 0;\n"); }
__device__ __forceinline__ void cp_wait1()  { asm volatile("cp.async.wait_group 1;\n"); }
__device__ __forceinline__ void ldsm4(uint32_t* r, uint32_t a) {
    asm volatile("ldmatrix.sync.aligned.m8n8.x4.shared.b16 {%0,%1,%2,%3},[%4];"
                 : "=r"(r[0]), "=r"(r[1]), "=r"(r[2]), "=r"(r[3]) : "r"(a));
}
__device__ __forceinline__ void ldsm4t(uint32_t* r, uint32_t a) {
    asm volatile("ldmatrix.sync.aligned.m8n8.x4.trans.shared.b16 {%0,%1,%2,%3},[%4];"
                 : "=r"(r[0]), "=r"(r[1]), "=r"(r[2]), "=r"(r[3]) : "r"(a));
}
__device__ __forceinline__ void mma16816(float* c, const uint32_t* a, const uint32_t* b) {
    asm volatile("mma.sync.aligned.m16n8k16.row.col.f32.f16.f16.f32 "
                 "{%0,%1,%2,%3},{%4,%5,%6,%7},{%8,%9},{%0,%1,%2,%3};"
                 : "+f"(c[0]), "+f"(c[1]), "+f"(c[2]), "+f"(c[3])
                 : "r"(a[0]), "r"(a[1]), "r"(a[2]), "r"(a[3]), "r"(b[0]), "r"(b[1]));
}
__device__ __forceinline__ void split2(float v0, float v1, __half2& h2, __half2& l2) {
    __half h0 = __float2half_rn(v0), h1 = __float2half_rn(v1);
    __half l0 = __float2half_rn(v0 - __half2float(h0));
    __half l1 = __float2half_rn(v1 - __half2float(h1));
    h2 = __halves2half2(h0, h1);
    l2 = __halves2half2(l0, l1);
}
__device__ __forceinline__ uint32_t h2u(__half2 v) {
    uint32_t r; memcpy(&r, &v, 4); return r;
}

// ---------------- fp32 -> (hi[, lo]) fp16 split ----------------
__global__ void split_k(const float* __restrict__ s, __half* __restrict__ h,
                        __half* __restrict__ l, long long n4) {
    long long i = (long long)blockIdx.x * blockDim.x + threadIdx.x;
    if (i >= n4) return;
    float4 v = reinterpret_cast<const float4*>(s)[i];
    __half2 h0, l0, h1, l1;
    split2(v.x, v.y, h0, l0);
    split2(v.z, v.w, h1, l1);
    reinterpret_cast<__half2*>(h)[i * 2 + 0] = h0;
    reinterpret_cast<__half2*>(h)[i * 2 + 1] = h1;
    if (l) {
        reinterpret_cast<__half2*>(l)[i * 2 + 0] = l0;
        reinterpret_cast<__half2*>(l)[i * 2 + 1] = l1;
    }
}

// strided split: src[K][N] fp32 -> dst[K][ldd] (hi,lo) at col0; z = layer
__global__ void splits_k(const float* __restrict__ s, __half* __restrict__ dh,
                         __half* __restrict__ dl, int N, int ldd, int col0,
                         long long perz_src, long long perz_dst) {
    const float* sp = s + (long long)blockIdx.z * perz_src;
    __half* dhp = dh + (long long)blockIdx.z * perz_dst;
    __half* dlp = dl + (long long)blockIdx.z * perz_dst;
    long long i = (long long)blockIdx.x * blockDim.x + threadIdx.x;
    long long e = i * 4;
    if (e >= perz_src) return;
    int row = (int)(e / N), col = (int)(e % N);
    float4 v = *reinterpret_cast<const float4*>(sp + e);
    __half2 h0, l0, h1, l1;
    split2(v.x, v.y, h0, l0);
    split2(v.z, v.w, h1, l1);
    __half2* oh = reinterpret_cast<__half2*>(dhp + (long long)row * ldd + col0 + col);
    __half2* ol = reinterpret_cast<__half2*>(dlp + (long long)row * ldd + col0 + col);
    oh[0] = h0; oh[1] = h1;
    ol[0] = l0; ol[1] = l1;
}

// combined qkv bias
__global__ void catb_k(const float* __restrict__ bq, const float* __restrict__ bk,
                       const float* __restrict__ bv, float* __restrict__ dst) {
    int i = blockIdx.x * 256 + threadIdx.x;
    if (i >= NL * DMOD) return;
    int lyr = i / DMOD, d = i % DMOD;
    dst[lyr * 3072 + d]        = bq[i];
    dst[lyr * 3072 + 1024 + d] = bk[i];
    dst[lyr * 3072 + 2048 + d] = bv[i];
}

// ---------------- split-fp16 tensor-core GEMM ----------------
struct HP {
    const __half *Ah, *Al, *Bh, *Bl;
    float* Cf; __half *Chi, *Clo;
    const float* bias;
    int M, N, K, lda, ldb, ldc, bh;
    long long sA1, sA2, sB1, sB2, sC1, sC2, sBias1;
    const int* counts; const int* rowmap; int mapStride;
    const float* rowsc; float* scat; int scat_ld;
};

enum { EP_F32 = 0, EP_SPLIT = 1, EP_SPLIT_RELU = 2, EP_SCATTER = 3 };

// dyn smem bytes: NSTAGE stages of (A-hi [+A-lo] + B-hi [+B-lo])
#define HSB(BM_,NT_,NS_) (2 * (NS_) * ((BM_) * 40 * (((NT_) >= 2) ? 2 : 1) \
                                       + 4352 * (((NT_) == 3) ? 2 : 1)))

// NTERM: 3 = ah*bh + al*bh + ah*bl ; 2 = ah*bh + al*bh ; 1 = ah*bh
// NSTAGE: 2 (two barriers/iter) or 3 (one barrier/iter; use when smem is small)
template<int BM, bool GATHER, int MODE, int NTERM, int NSTAGE>
__global__ __launch_bounds__(256) void hgemm_k(HP p) {
    constexpr int BN = 128, BK = 32;
    constexpr int WROWS = 2, WCOLS = 4;
    constexpr int WM = BM / WROWS, WN = 32, MM = WM / 16, MN = 4;
    constexpr int APAD = 40, BPAD = 136;
    constexpr int ASTG = BM * 40;                      // halves per A stage
    constexpr int NAH  = (NTERM >= 2) ? 2 : 1;
    constexpr int OFF_ALO = NSTAGE * ASTG;             // A-lo base (if present)
    constexpr int OFF_BHI = NSTAGE * ASTG * NAH;
    constexpr int OFF_BLO = OFF_BHI + NSTAGE * 4352;
    extern __shared__ __half sm[];

    const int z  = blockIdx.z;
    const int b2 = z / p.bh, b1 = z % p.bh;
    const __half* Ah = p.Ah + b2 * p.sA2 + b1 * p.sA1;
    const __half* Al = (NTERM >= 2) ? p.Al + b2 * p.sA2 + b1 * p.sA1 : nullptr;
    const __half* Bh = p.Bh + b2 * p.sB2 + b1 * p.sB1;
    const __half* Bl = (NTERM == 3) ? p.Bl + b2 * p.sB2 + b1 * p.sB1 : nullptr;
    const int M = p.counts ? p.counts[z] : p.M;
    const int row0 = blockIdx.y * BM;
    if (row0 >= M) return;
    const int col0 = blockIdx.x * BN;

    const int tid = threadIdx.x;
    const int l   = tid & 31;
    const int wid = tid >> 5;
    const int wr  = wid / WCOLS, wc = wid % WCOLS;

    const int* rmap = (GATHER || MODE == EP_SCATTER)
                      ? p.rowmap + (long long)z * p.mapStride : nullptr;

    float acc[MM][MN][4];
#pragma unroll
    for (int i = 0; i < MM; i++)
#pragma unroll
        for (int j = 0; j < MN; j++)
#pragma unroll
            for (int r = 0; r < 4; r++) acc[i][j][r] = 0.f;

    // A loader: BM*4 16B-chunks per array; 1 (BM=64) or 2 (BM=128) per thread
    const int aRow0 = tid >> 2, aK0 = (tid & 3) * 8;
    const int aRow1 = aRow0 + 64;
    const bool av0 = (row0 + aRow0) < M;
    const bool av1 = (BM == 128) && ((row0 + aRow1) < M);
    long long aB0 = 0, aB1 = 0;
    if (GATHER) {
        aB0 = (long long)(av0 ? rmap[row0 + aRow0] : 0) * p.lda;
        if (BM == 128) aB1 = (long long)(av1 ? rmap[row0 + aRow1] : 0) * p.lda;
    } else {
        aB0 = (long long)(row0 + aRow0) * p.lda;
        if (BM == 128) aB1 = (long long)(row0 + aRow1) * p.lda;
    }
    const int bRow0 = tid >> 4, bN0 = (tid & 15) * 8;
    const int bRow1 = bRow0 + 16;

    auto load_stage = [&](int kt, int st) {
        const int k0 = kt * BK;
        __half* Asth = sm + st * ASTG;
        cp16(Asth + aRow0 * APAD + aK0, Ah + aB0 + k0 + aK0, av0);
        if (BM == 128) cp16(Asth + aRow1 * APAD + aK0, Ah + aB1 + k0 + aK0, av1);
        if (NTERM >= 2) {
            __half* Astl = sm + OFF_ALO + st * ASTG;
            cp16(Astl + aRow0 * APAD + aK0, Al + aB0 + k0 + aK0, av0);
            if (BM == 128) cp16(Astl + aRow1 * APAD + aK0, Al + aB1 + k0 + aK0, av1);
        }
        __half* Bsth = sm + OFF_BHI + st * 4352;
        cp16(Bsth + bRow0 * BPAD + bN0, Bh + (long long)(k0 + bRow0) * p.ldb + col0 + bN0, true);
        cp16(Bsth + bRow1 * BPAD + bN0, Bh + (long long)(k0 + bRow1) * p.ldb + col0 + bN0, true);
        if (NTERM == 3) {
            __half* Bstl = sm + OFF_BLO + st * 4352;
            cp16(Bstl + bRow0 * BPAD + bN0, Bl + (long long)(k0 + bRow0) * p.ldb + col0 + bN0, true);
            cp16(Bstl + bRow1 * BPAD + bN0, Bl + (long long)(k0 + bRow1) * p.ldb + col0 + bN0, true);
        }
        cp_commit();
    };

    auto compute = [&](int st) {
        __half* Asth = sm + st * ASTG;
        __half* Astl = sm + OFF_ALO + st * ASTG;
        __half* Bsth = sm + OFF_BHI + st * 4352;
        __half* Bstl = sm + OFF_BLO + st * 4352;
#pragma unroll
        for (int ks = 0; ks < 2; ks++) {
            uint32_t fah[MM][4], fal[MM][4], fbh[MN][2], fbl[MN][2];
#pragma unroll
            for (int mi = 0; mi < MM; mi++) {
                const int r = wr * WM + mi * 16 + (l & 15);
                const int c = ks * 16 + ((l >> 4) << 3);
                ldsm4(fah[mi], smem_u32(Asth + r * APAD + c));
                if (NTERM >= 2) ldsm4(fal[mi], smem_u32(Astl + r * APAD + c));
            }
#pragma unroll
            for (int nj = 0; nj < MN / 2; nj++) {
                const int r = ks * 16 + (l & 15);
                const int c = wc * WN + nj * 16 + ((l >> 4) << 3);
                uint32_t r4[4];
                ldsm4t(r4, smem_u32(Bsth + r * BPAD + c));
                fbh[2*nj][0] = r4[0]; fbh[2*nj][1] = r4[1];
                fbh[2*nj+1][0] = r4[2]; fbh[2*nj+1][1] = r4[3];
                if (NTERM == 3) {
                    ldsm4t(r4, smem_u32(Bstl + r * BPAD + c));
                    fbl[2*nj][0] = r4[0]; fbl[2*nj][1] = r4[1];
                    fbl[2*nj+1][0] = r4[2]; fbl[2*nj+1][1] = r4[3];
                }
            }
#pragma unroll
            for (int mi = 0; mi < MM; mi++)
#pragma unroll
                for (int ni = 0; ni < MN; ni++) {
                    mma16816(acc[mi][ni], fah[mi], fbh[ni]);
                    if (NTERM >= 2) mma16816(acc[mi][ni], fal[mi], fbh[ni]);
                    if (NTERM == 3) mma16816(acc[mi][ni], fah[mi], fbl[ni]);
                }
        }
    };

    const int nK = p.K / BK;
    if (NSTAGE == 2) {
        load_stage(0, 0);
        for (int kt = 0; kt < nK; kt++) {
            const int st = kt & 1;
            if (kt + 1 < nK) {
                load_stage(kt + 1, st ^ 1);
                cp_wait1();
            } else {
                cp_wait0();
            }
            __syncthreads();
            compute(st);
            __syncthreads();
        }
    } else {
        // 3-stage, ONE barrier per iteration (R10 loop; occupancy-safe here)
        load_stage(0, 0);
        load_stage(1, 1);
        int st = 0;
        for (int kt = 0; kt < nK; kt++) {
            if (kt + 1 < nK) cp_wait1(); else cp_wait0();
            __syncthreads();
            if (kt + 2 < nK) {
                int s2 = st + 2; if (s2 >= 3) s2 -= 3;
                load_stage(kt + 2, s2);
            }
            compute(st);
            if (++st == 3) st = 0;
        }
    }

    const float* bias = p.bias ? p.bias + b1 * p.sBias1 : nullptr;
    float*  Cf  = p.Cf  ? p.Cf  + b2 * p.sC2 + b1 * p.sC1 : nullptr;
    __half* Chi = p.Chi ? p.Chi + b2 * p.sC2 + b1 * p.sC1 : nullptr;
    __half* Clo = p.Clo ? p.Clo + b2 * p.sC2 + b1 * p.sC1 : nullptr;
#pragma unroll
    for (int mi = 0; mi < MM; mi++) {
#pragma unroll
        for (int hh = 0; hh < 2; hh++) {
            const int r = row0 + wr * WM + mi * 16 + (l >> 2) + hh * 8;
            if (r >= M) continue;
#pragma unroll
            for (int ni = 0; ni < MN; ni++) {
                const int c = col0 + wc * WN + ni * 8 + (l & 3) * 2;
                float v0 = acc[mi][ni][hh * 2 + 0];
                float v1 = acc[mi][ni][hh * 2 + 1];
                if (bias) { v0 += bias[c]; v1 += bias[c + 1]; }
                if (MODE == EP_SPLIT_RELU) { v0 = fmaxf(v0, 0.f); v1 = fmaxf(v1, 0.f); }
                if (MODE == EP_SCATTER) {
                    const int tok = rmap[r];
                    const float w = p.rowsc[(long long)z * p.mapStride + r];
                    atomicAdd(p.scat + (long long)tok * p.scat_ld + c,     w * v0);
                    atomicAdd(p.scat + (long long)tok * p.scat_ld + c + 1, w * v1);
                } else if (MODE == EP_F32) {
                    *reinterpret_cast<float2*>(Cf + (long long)r * p.ldc + c) =
                        make_float2(v0, v1);
                } else {
                    __half2 h2, l2;
                    split2(v0, v1, h2, l2);
                    *reinterpret_cast<__half2*>(Chi + (long long)r * p.ldc + c) = h2;
                    *reinterpret_cast<__half2*>(Clo + (long long)r * p.ldc + c) = l2;
                }
            }
        }
    }
}

// ---------------- fused flash attention ----------------
#define FA_SMEM 108544
__global__ __launch_bounds__(256) void fa_k(const __half* __restrict__ qkvh,
                                            const __half* __restrict__ qkvl,
                                            __half* __restrict__ aoh,
                                            __half* __restrict__ aol) {
    extern __shared__ __align__(16) __half fs[];
    __half* Qh  = fs;            // [128][72]
    __half* Ql  = fs + 9216;
    __half* Kth = fs + 18432;    // [64][136] transposed K chunk
    __half* Ktl = fs + 27136;
    __half* Vh  = fs + 35840;    // [128][72] V chunk
    __half* Vl  = fs + 45056;
    const int z = blockIdx.z, b = z / NH, h = z % NH;
    const int q0 = blockIdx.y * 128;
    const int tid = threadIdx.x, l = tid & 31, w = tid >> 5;

#pragma unroll
    for (int i = 0; i < 4; i++) {
        int c = tid + i * 256;
        int row = c >> 3, k8 = (c & 7) * 8;
        long long g = ((long long)(b * SEQ + q0 + row)) * 3072 + h * 64 + k8;
        cp16(Qh + row * 72 + k8, qkvh + g, true);
        cp16(Ql + row * 72 + k8, qkvl + g, true);
    }
    cp_commit();

    float accO[8][4];
#pragma unroll
    for (int i = 0; i < 8; i++)
#pragma unroll
        for (int j = 0; j < 4; j++) accO[i][j] = 0.f;
    float m0 = -1e30f, m1 = -1e30f, s0 = 0.f, s1 = 0.f;

    uint32_t qah[4][4], qal[4][4];

    for (int c = 0; c < 8; c++) {
        const int k0r = c * 128;
        __syncthreads();
#pragma unroll
        for (int i = 0; i < 4; i++) {
            int cc = tid + i * 256;
            int n = cc >> 3, k8 = (cc & 7) * 8;
            long long gk = ((long long)(b * SEQ + k0r + n)) * 3072 + 1024 + h * 64 + k8;
            uint4 rh = *reinterpret_cast<const uint4*>(qkvh + gk);
            uint4 rl = *reinterpret_cast<const uint4*>(qkvl + gk);
            __half hh[8], ll[8];
            memcpy(hh, &rh, 16); memcpy(ll, &rl, 16);
#pragma unroll
            for (int j = 0; j < 8; j++) {
                Kth[(k8 + j) * 136 + n] = hh[j];
                Ktl[(k8 + j) * 136 + n] = ll[j];
            }
            long long gv = ((long long)(b * SEQ + k0r + n)) * 3072 + 2048 + h * 64 + k8;
            cp16(Vh + n * 72 + k8, qkvh + gv, true);
            cp16(Vl + n * 72 + k8, qkvl + gv, true);
        }
        cp_commit();
        cp_wait0();
        __syncthreads();
        if (c == 0) {
#pragma unroll
            for (int ks = 0; ks < 4; ks++) {
                const int r = w * 16 + (l & 15);
                const int cq = ks * 16 + ((l >> 4) << 3);
                ldsm4(qah[ks], smem_u32(Qh + r * 72 + cq));
                ldsm4(qal[ks], smem_u32(Ql + r * 72 + cq));
            }
        }
        float sacc[16][4];
#pragma unroll
        for (int t = 0; t < 16; t++)
#pragma unroll
            for (int j = 0; j < 4; j++) sacc[t][j] = 0.f;
#pragma unroll
        for (int ks = 0; ks < 4; ks++) {
#pragma unroll
            for (int nj = 0; nj < 8; nj++) {
                const int r = ks * 16 + (l & 15);
                const int cc2 = nj * 16 + ((l >> 4) << 3);
                uint32_t r4h[4], r4l[4];
                ldsm4t(r4h, smem_u32(Kth + r * 136 + cc2));
                ldsm4t(r4l, smem_u32(Ktl + r * 136 + cc2));
                uint32_t bh0[2] = {r4h[0], r4h[1]}, bh1[2] = {r4h[2], r4h[3]};
                uint32_t bl0[2] = {r4l[0], r4l[1]}, bl1[2] = {r4l[2], r4l[3]};
                mma16816(sacc[2*nj],   qah[ks], bh0);
                mma16816(sacc[2*nj],   qal[ks], bh0);
                mma16816(sacc[2*nj],   qah[ks], bl0);
                mma16816(sacc[2*nj+1], qah[ks], bh1);
                mma16816(sacc[2*nj+1], qal[ks], bh1);
                mma16816(sacc[2*nj+1], qah[ks], bl1);
            }
        }
        const float scale = 0.125f;
        float nm0 = m0, nm1 = m1;
#pragma unroll
        for (int t = 0; t < 16; t++) {
            sacc[t][0] *= scale; sacc[t][1] *= scale;
            sacc[t][2] *= scale; sacc[t][3] *= scale;
            nm0 = fmaxf(nm0, fmaxf(sacc[t][0], sacc[t][1]));
            nm1 = fmaxf(nm1, fmaxf(sacc[t][2], sacc[t][3]));
        }
        nm0 = fmaxf(nm0, __shfl_xor_sync(0xffffffffu, nm0, 1));
        nm0 = fmaxf(nm0, __shfl_xor_sync(0xffffffffu, nm0, 2));
        nm1 = fmaxf(nm1, __shfl_xor_sync(0xffffffffu, nm1, 1));
        nm1 = fmaxf(nm1, __shfl_xor_sync(0xffffffffu, nm1, 2));
        const float al0 = __expf(m0 - nm0), al1 = __expf(m1 - nm1);
        m0 = nm0; m1 = nm1;
        float ls0 = 0.f, ls1 = 0.f;
#pragma unroll
        for (int t = 0; t < 16; t++) {
            sacc[t][0] = __expf(sacc[t][0] - m0);
            sacc[t][1] = __expf(sacc[t][1] - m0);
            sacc[t][2] = __expf(sacc[t][2] - m1);
            sacc[t][3] = __expf(sacc[t][3] - m1);
            ls0 += sacc[t][0] + sacc[t][1];
            ls1 += sacc[t][2] + sacc[t][3];
        }
        ls0 += __shfl_xor_sync(0xffffffffu, ls0, 1);
        ls0 += __shfl_xor_sync(0xffffffffu, ls0, 2);
        ls1 += __shfl_xor_sync(0xffffffffu, ls1, 1);
        ls1 += __shfl_xor_sync(0xffffffffu, ls1, 2);
        s0 = s0 * al0 + ls0;
        s1 = s1 * al1 + ls1;
#pragma unroll
        for (int t8 = 0; t8 < 8; t8++) {
            accO[t8][0] *= al0; accO[t8][1] *= al0;
            accO[t8][2] *= al1; accO[t8][3] *= al1;
        }
#pragma unroll
        for (int j = 0; j < 8; j++) {
            __half2 ph0, pl0, ph1, pl1, ph2, pl2, ph3, pl3;
            split2(sacc[2*j][0],   sacc[2*j][1],   ph0, pl0);
            split2(sacc[2*j][2],   sacc[2*j][3],   ph1, pl1);
            split2(sacc[2*j+1][0], sacc[2*j+1][1], ph2, pl2);
            split2(sacc[2*j+1][2], sacc[2*j+1][3], ph3, pl3);
            uint32_t pah[4] = {h2u(ph0), h2u(ph1), h2u(ph2), h2u(ph3)};
            uint32_t pal[4] = {h2u(pl0), h2u(pl1), h2u(pl2), h2u(pl3)};
#pragma unroll
            for (int vn = 0; vn < 4; vn++) {
                const int r = j * 16 + (l & 15);
                const int cv = vn * 16 + ((l >> 4) << 3);
                uint32_t r4h[4], r4l[4];
                ldsm4t(r4h, smem_u32(Vh + r * 72 + cv));
                ldsm4t(r4l, smem_u32(Vl + r * 72 + cv));
                uint32_t bh0[2] = {r4h[0], r4h[1]}, bh1[2] = {r4h[2], r4h[3]};
                uint32_t bl0[2] = {r4l[0], r4l[1]}, bl1[2] = {r4l[2], r4l[3]};
                mma16816(accO[2*vn],   pah, bh0);
                mma16816(accO[2*vn],   pal, bh0);
                mma16816(accO[2*vn],   pah, bl0);
                mma16816(accO[2*vn+1], pah, bh1);
                mma16816(accO[2*vn+1], pal, bh1);
                mma16816(accO[2*vn+1], pah, bl1);
            }
        }
    }
    const float inv0 = 1.f / s0, inv1 = 1.f / s1;
    const int r0 = q0 + w * 16 + (l >> 2);
    const int r1 = r0 + 8;
    const long long t0g = (long long)(b * SEQ + r0) * DMOD + h * 64;
    const long long t1g = (long long)(b * SEQ + r1) * DMOD + h * 64;
#pragma unroll
    for (int t8 = 0; t8 < 8; t8++) {
        const int cdim = t8 * 8 + (l & 3) * 2;
        __half2 hh, llh;
        split2(accO[t8][0] * inv0, accO[t8][1] * inv0, hh, llh);
        *reinterpret_cast<__half2*>(aoh + t0g + cdim) = hh;
        *reinterpret_cast<__half2*>(aol + t0g + cdim) = llh;
        split2(accO[t8][2] * inv1, accO[t8][3] * inv1, hh, llh);
        *reinterpret_cast<__half2*>(aoh + t1g + cdim) = hh;
        *reinterpret_cast<__half2*>(aol + t1g + cdim) = llh;
    }
}

// ---------------- embedding + positional encoding ----------------
__global__ void embed_k(const int* __restrict__ src, const float* __restrict__ emb,
                        float* __restrict__ xf, __half* __restrict__ xh,
                        __half* __restrict__ xl) {
    const int t = blockIdx.x;
    const int s = t % SEQ;
    const int tok = src[t];
    const float c = -logf(10000.0f) / (float)DMOD;
    for (int d = threadIdx.x; d < DMOD; d += blockDim.x) {
        const int i = d >> 1;
        const float div = expf((float)(2 * i) * c);
        const float ang = (float)s * div;
        const float pe = (d & 1) ? cosf(ang) : sinf(ang);
        const float v = emb[(long long)tok * DMOD + d] * 32.0f + pe;
        xf[(long long)t * DMOD + d] = v;
        __half h = __float2half_rn(v);
        xh[(long long)t * DMOD + d] = h;
        xl[(long long)t * DMOD + d] = __float2half_rn(v - __half2float(h));
    }
}

// ---------------- layernorm ----------------
__global__ void ln_k(const float* __restrict__ a, const float* __restrict__ res,
                     const float* __restrict__ g, const float* __restrict__ be,
                     float* __restrict__ of, __half* __restrict__ oh,
                     __half* __restrict__ ol) {
    const int row = blockIdx.x;
    const int tid = threadIdx.x;
    float4 v = reinterpret_cast<const float4*>(a + (long long)row * DMOD)[tid];
    if (res) {
        float4 r = reinterpret_cast<const float4*>(res + (long long)row * DMOD)[tid];
        v.x += r.x; v.y += r.y; v.z += r.z; v.w += r.w;
    }
    float s  = v.x + v.y + v.z + v.w;
    float sq = v.x*v.x + v.y*v.y + v.z*v.z + v.w*v.w;
    __shared__ float rs[8], rq[8];
    for (int o = 16; o > 0; o >>= 1) {
        s  += __shfl_xor_sync(0xffffffffu, s,  o);
        sq += __shfl_xor_sync(0xffffffffu, sq, o);
    }
    if ((tid & 31) == 0) { rs[tid >> 5] = s; rq[tid >> 5] = sq; }
    __syncthreads();
    __shared__ float s_mu, s_inv;
    if (tid == 0) {
        float S = 0.f, Q = 0.f;
        for (int i = 0; i < 8; i++) { S += rs[i]; Q += rq[i]; }
        const float mu  = S / (float)DMOD;
        const float var = Q / (float)DMOD - mu * mu;
        s_mu = mu; s_inv = rsqrtf(var + 1e-5f);
    }
    __syncthreads();
    const float mu = s_mu, inv = s_inv;
    const float4 gv = reinterpret_cast<const float4*>(g)[tid];
    const float4 bv = reinterpret_cast<const float4*>(be)[tid];
    float o0 = (v.x - mu) * inv * gv.x + bv.x;
    float o1 = (v.y - mu) * inv * gv.y + bv.y;
    float o2 = (v.z - mu) * inv * gv.z + bv.z;
    float o3 = (v.w - mu) * inv * gv.w + bv.w;
    if (of) reinterpret_cast<float4*>(of + (long long)row * DMOD)[tid] = make_float4(o0, o1, o2, o3);
    __half2 h0, l0, h1, l1;
    split2(o0, o1, h0, l0);
    split2(o2, o3, h1, l1);
    reinterpret_cast<__half2*>(oh + (long long)row * DMOD)[tid * 2 + 0] = h0;
    reinterpret_cast<__half2*>(oh + (long long)row * DMOD)[tid * 2 + 1] = h1;
    reinterpret_cast<__half2*>(ol + (long long)row * DMOD)[tid * 2 + 0] = l0;
    reinterpret_cast<__half2*>(ol + (long long)row * DMOD)[tid * 2 + 1] = l1;
}

// ---------------- zero moe accumulator + counters ----------------
__global__ void zero_k(float* __restrict__ moe, int* __restrict__ cnt) {
    long long i = (long long)blockIdx.x * blockDim.x + threadIdx.x;
    const long long n = (long long)TTOK * DMOD;
    for (; i < n; i += (long long)gridDim.x * blockDim.x) moe[i] = 0.f;
    if (blockIdx.x == 0 && threadIdx.x < NE) cnt[threadIdx.x] = 0;
}

// ---------------- gate ----------------
__global__ void gate_k(const float* __restrict__ x, const float* __restrict__ gw,
                       const float* __restrict__ gb, int* __restrict__ cnt,
                       int* __restrict__ perm, float* __restrict__ pw) {
    const int t = blockIdx.x;
    const int tid = threadIdx.x;
    float acc[NE];
#pragma unroll
    for (int e = 0; e < NE; e++) acc[e] = 0.f;
    for (int d = tid; d < DMOD; d += 256) {
        const float xv = x[(long long)t * DMOD + d];
        const float* grow = gw + (long long)d * NE;
#pragma unroll
        for (int e = 0; e < NE; e++) acc[e] += xv * grow[e];
    }
    __shared__ float sh[NE][8];
    const int lane = tid & 31, wid = tid >> 5;
#pragma unroll
    for (int e = 0; e < NE; e++) {
        float s = acc[e];
        for (int o = 16; o > 0; o >>= 1) s += __shfl_xor_sync(0xffffffffu, s, o);
        if (lane == 0) sh[e][wid] = s;
    }
    __syncthreads();
    if (tid == 0) {
        float lg[NE];
#pragma unroll
        for (int e = 0; e < NE; e++) {
            float s = 0.f;
            for (int w = 0; w < 8; w++) s += sh[e][w];
            lg[e] = s + gb[e];
        }
        int i0 = 0;
        for (int e = 1; e < NE; e++) if (lg[e] > lg[i0]) i0 = e;
        int i1 = (i0 == 0) ? 1 : 0;
        for (int e = 0; e < NE; e++) if (e != i0 && lg[e] > lg[i1]) i1 = e;
        const float e1 = expf(lg[i1] - lg[i0]);
        const float inv = 1.0f / (1.0f + e1);
        int p0 = atomicAdd(&cnt[i0], 1); perm[i0 * TTOK + p0] = t; pw[i0 * TTOK + p0] = inv;
        int p1 = atomicAdd(&cnt[i1], 1); perm[i1 * TTOK + p1] = t; pw[i1 * TTOK + p1] = e1 * inv;
    }
}

// ---------------- host orchestration ----------------
static inline void splitw(const float* s, __half* h, __half* l, long long n) {
    long long n4 = n / 4;
    split_k<<<(unsigned)((n4 + 255) / 256), 256>>>(s, h, l, n4);
}

extern "C" void kernel_launch(void* const* d_in, const int* in_sizes, int n_in,
                              void* d_out, int out_size) {
    (void)in_sizes; (void)n_in; (void)out_size;
    const int*   src    = (const int*)  d_in[0];
    const float* emb    = (const float*)d_in[1];
    const float* Wq     = (const float*)d_in[2];
    const float* bq     = (const float*)d_in[3];
    const float* Wk     = (const float*)d_in[4];
    const float* bk     = (const float*)d_in[5];
    const float* Wv     = (const float*)d_in[6];
    const float* bv     = (const float*)d_in[7];
    const float* Wo     = (const float*)d_in[8];
    const float* bo     = (const float*)d_in[9];
    const float* ln1_g  = (const float*)d_in[10];
    const float* ln1_b  = (const float*)d_in[11];
    const float* W1     = (const float*)d_in[12];
    const float* b1     = (const float*)d_in[13];
    const float* W2     = (const float*)d_in[14];
    const float* b2     = (const float*)d_in[15];
    const float* ln2_g  = (const float*)d_in[16];
    const float* ln2_b  = (const float*)d_in[17];
    const float* gate_W = (const float*)d_in[18];
    const float* gate_b = (const float*)d_in[19];
    const float* eW1    = (const float*)d_in[20];
    const float* eb1    = (const float*)d_in[21];
    const float* eW2    = (const float*)d_in[22];
    const float* eb2    = (const float*)d_in[23];
    const float* fln_g  = (const float*)d_in[24];
    const float* fln_b  = (const float*)d_in[25];
    const float* out_W  = (const float*)d_in[26];
    const float* out_b  = (const float*)d_in[27];

#define SYM(v, s) cudaGetSymbolAddress((void**)&v, s)
    __half *qkvw_h,*qkvw_l,*wo_h,*wo_l,*w1_h,*w1_l,*w2_h,*w2_l,*ew1_h,*ew2_h,*ow_h;
    __half *x_h,*x_l,*qkv_h,*qkv_l,*ao_h,*ao_l;
    __half *ffh_h,*ffh_l,*mh_h,*mh_l,*xn_h,*xn_l;
    float *bqkv,*xf,*t1f,*moef,*xnf,*pw;
    int *cnt,*perm;
    SYM(qkvw_h,g_qkvw_h); SYM(qkvw_l,g_qkvw_l); SYM(bqkv,g_bqkv);
    SYM(wo_h,g_wo_h); SYM(wo_l,g_wo_l);
    SYM(w1_h,g_w1_h); SYM(w1_l,g_w1_l); SYM(w2_h,g_w2_h); SYM(w2_l,g_w2_l);
    SYM(ew1_h,g_ew1_h); SYM(ew2_h,g_ew2_h); SYM(ow_h,g_ow_h);
    SYM(x_h,g_x_h); SYM(x_l,g_x_l); SYM(qkv_h,g_qkv_h); SYM(qkv_l,g_qkv_l);
    SYM(ao_h,g_ao_h); SYM(ao_l,g_ao_l);
    SYM(ffh_h,g_ffh_h); SYM(ffh_l,g_ffh_l); SYM(mh_h,g_mh_h); SYM(mh_l,g_mh_l);
    SYM(xn_h,g_xn_h); SYM(xn_l,g_xn_l);
    SYM(xf,g_xf); SYM(t1f,g_t1f); SYM(moef,g_moef); SYM(xnf,g_xnf);
    SYM(pw,g_pw); SYM(cnt,g_cnt); SYM(perm,g_perm);
#undef SYM

    cudaFuncSetAttribute(fa_k, cudaFuncAttributeMaxDynamicSharedMemorySize, FA_SMEM);
    cudaFuncSetAttribute(hgemm_k<128,false,EP_SPLIT,3,2>,      cudaFuncAttributeMaxDynamicSharedMemorySize, HSB(128,3,2));
    cudaFuncSetAttribute(hgemm_k<128,false,EP_SPLIT_RELU,3,2>, cudaFuncAttributeMaxDynamicSharedMemorySize, HSB(128,3,2));
    cudaFuncSetAttribute(hgemm_k<64, false,EP_F32,3,2>,        cudaFuncAttributeMaxDynamicSharedMemorySize, HSB(64,3,2));
    cudaFuncSetAttribute(hgemm_k<128,true, EP_SPLIT_RELU,1,3>, cudaFuncAttributeMaxDynamicSharedMemorySize, HSB(128,1,3));
    cudaFuncSetAttribute(hgemm_k<128,false,EP_SCATTER,1,3>,    cudaFuncAttributeMaxDynamicSharedMemorySize, HSB(128,1,3));
    cudaFuncSetAttribute(hgemm_k<128,false,EP_F32,1,3>,        cudaFuncAttributeMaxDynamicSharedMemorySize, HSB(128,1,3));

    {
        long long perz = (long long)DMOD * DMOD;
        unsigned blks = (unsigned)((perz / 4 + 255) / 256);
        splits_k<<<dim3(blks,1,NL),256>>>(Wq, qkvw_h, qkvw_l, DMOD, 3072, 0,    perz, (long long)DMOD*3072);
        splits_k<<<dim3(blks,1,NL),256>>>(Wk, qkvw_h, qkvw_l, DMOD, 3072, 1024, perz, (long long)DMOD*3072);
        splits_k<<<dim3(blks,1,NL),256>>>(Wv, qkvw_h, qkvw_l, DMOD, 3072, 2048, perz, (long long)DMOD*3072);
        catb_k<<<(NL*DMOD + 255)/256, 256>>>(bq, bk, bv, bqkv);
    }
    splitw(Wo,  wo_h,  wo_l,  (long long)NL * DMOD * DMOD);
    splitw(W1,  w1_h,  w1_l,  (long long)NL * DMOD * FDIM);
    splitw(W2,  w2_h,  w2_l,  (long long)NL * FDIM * DMOD);
    splitw(eW1, ew1_h, nullptr, (long long)NE * DMOD * FDIM);
    splitw(eW2, ew2_h, nullptr, (long long)NE * FDIM * DMOD);
    splitw(out_W, ow_h, nullptr, (long long)DMOD * VOC);

    embed_k<<<TTOK, 256>>>(src, emb, xf, x_h, x_l);

    for (int l = 0; l < NL; l++) {
        HP p;
        // fused QKV: x @ Wqkv (N=3072)
        p = HP{};
        p.Ah = x_h; p.Al = x_l;
        p.Bh = qkvw_h + (long long)l*DMOD*3072; p.Bl = qkvw_l + (long long)l*DMOD*3072;
        p.Chi = qkv_h; p.Clo = qkv_l; p.bias = bqkv + l*3072;
        p.M = TTOK; p.N = 3072; p.K = DMOD;
        p.lda = DMOD; p.ldb = 3072; p.ldc = 3072; p.bh = 1;
        hgemm_k<128,false,EP_SPLIT,3,2><<<dim3(24,16,1),256,HSB(128,3,2)>>>(p);
        // fused flash attention -> ao (split)
        fa_k<<<dim3(1,8,NBAT*NH),256,FA_SMEM>>>(qkv_h, qkv_l, ao_h, ao_l);
        // ao @ Wo + bo (BM=64: 256 CTAs)
        p = HP{};
        p.Ah = ao_h; p.Al = ao_l;
        p.Bh = wo_h + (long long)l*DMOD*DMOD; p.Bl = wo_l + (long long)l*DMOD*DMOD;
        p.Cf = t1f; p.bias = bo + l*DMOD;
        p.M = TTOK; p.N = DMOD; p.K = DMOD;
        p.lda = DMOD; p.ldb = DMOD; p.ldc = DMOD; p.bh = 1;
        hgemm_k<64,false,EP_F32,3,2><<<dim3(8,32,1),256,HSB(64,3,2)>>>(p);
        ln_k<<<TTOK, 256>>>(t1f, xf, ln1_g + l*DMOD, ln1_b + l*DMOD, xf, x_h, x_l);
        // ffh = relu(x @ W1 + b1)
        p = HP{};
        p.Ah = x_h; p.Al = x_l;
        p.Bh = w1_h + (long long)l*DMOD*FDIM; p.Bl = w1_l + (long long)l*DMOD*FDIM;
        p.Chi = ffh_h; p.Clo = ffh_l; p.bias = b1 + l*FDIM;
        p.M = TTOK; p.N = FDIM; p.K = DMOD;
        p.lda = DMOD; p.ldb = FDIM; p.ldc = FDIM; p.bh = 1;
        hgemm_k<128,false,EP_SPLIT_RELU,3,2><<<dim3(32,16,1),256,HSB(128,3,2)>>>(p);
        // ff = ffh @ W2 + b2 (BM=64: 256 CTAs)
        p = HP{};
        p.Ah = ffh_h; p.Al = ffh_l;
        p.Bh = w2_h + (long long)l*FDIM*DMOD; p.Bl = w2_l + (long long)l*FDIM*DMOD;
        p.Cf = t1f; p.bias = b2 + l*DMOD;
        p.M = TTOK; p.N = DMOD; p.K = FDIM;
        p.lda = FDIM; p.ldb = DMOD; p.ldc = DMOD; p.bh = 1;
        hgemm_k<64,false,EP_F32,3,2><<<dim3(8,32,1),256,HSB(64,3,2)>>>(p);
        ln_k<<<TTOK, 256>>>(t1f, xf, ln2_g + l*DMOD, ln2_b + l*DMOD, xf, x_h, x_l);
    }

    // MoE (post-gate: NTERM=1 hi-only experts, 3-stage pipeline)
    zero_k<<<2048, 256>>>(moef, cnt);
    gate_k<<<TTOK, 256>>>(xf, gate_W, gate_b, cnt, perm, pw);
    {
        HP p = HP{};
        p.Ah = x_h; p.Bh = ew1_h;
        p.Chi = mh_h; p.Clo = mh_l; p.bias = eb1;
        p.M = TTOK; p.N = FDIM; p.K = DMOD;
        p.lda = DMOD; p.ldb = FDIM; p.ldc = FDIM; p.bh = NE;
        p.sB1 = (long long)DMOD * FDIM; p.sC1 = (long long)TTOK * FDIM; p.sBias1 = FDIM;
        p.counts = cnt; p.rowmap = perm; p.mapStride = TTOK;
        hgemm_k<128,true,EP_SPLIT_RELU,1,3><<<dim3(32,16,NE),256,HSB(128,1,3)>>>(p);
    }
    {
        HP p = HP{};
        p.Ah = mh_h; p.Bh = ew2_h; p.bias = eb2;
        p.M = TTOK; p.N = DMOD; p.K = FDIM;
        p.lda = FDIM; p.ldb = DMOD; p.bh = NE;
        p.sA1 = (long long)TTOK * FDIM; p.sB1 = (long long)FDIM * DMOD; p.sBias1 = DMOD;
        p.counts = cnt; p.rowmap = perm; p.mapStride = TTOK;
        p.rowsc = pw; p.scat = moef; p.scat_ld = DMOD;
        hgemm_k<128,false,EP_SCATTER,1,3><<<dim3(8,16,NE),256,HSB(128,1,3)>>>(p);
    }
    ln_k<<<TTOK, 256>>>(moef, nullptr, fln_g, fln_b, xnf, xn_h, xn_l);
    // output projection -> d_out (hi-only NTERM=1, 3-stage)
    {
        HP p = HP{};
        p.Ah = xn_h; p.Bh = ow_h;
        p.Cf = (float*)d_out; p.bias = out_b;
        p.M = TTOK; p.N = VOC; p.K = DMOD;
        p.lda = DMOD; p.ldb = VOC; p.ldc = VOC; p.bh = 1;
        hgemm_k<128,false,EP_F32,1,3><<<dim3(250,16,1),256,HSB(128,1,3)>>>(p);
    }
}

// round 16
// speedup vs baseline: 1.0523x; 1.0034x over previous
#include <cuda_runtime.h>
#include <cuda_fp16.h>
#include <math.h>
#include <stdint.h>
#include <string.h>

#define TTOK 2048
#define DMOD 1024
#define FDIM 4096
#define SEQ  1024
#define NBAT 2
#define NH   16
#define HDM  64
#define NE   8
#define VOC  32000
#define NL   3

// ---------------- scratch (static device globals; no allocation) ----------------
__device__ __half g_qkvw_h[NL*DMOD*3072], g_qkvw_l[NL*DMOD*3072];
__device__ float  g_bqkv  [NL*3072];
__device__ __half g_wo_h [NL*DMOD*DMOD], g_wo_l [NL*DMOD*DMOD];
__device__ __half g_w1_h [NL*DMOD*FDIM], g_w1_l [NL*DMOD*FDIM];
__device__ __half g_w2_h [NL*FDIM*DMOD], g_w2_l [NL*FDIM*DMOD];
__device__ __half g_ew1_h[NE*DMOD*FDIM];
__device__ __half g_ew2_h[NE*FDIM*DMOD];
__device__ __half g_ow_h [DMOD*VOC];
// activations split hi/lo
__device__ __half g_x_h  [TTOK*DMOD], g_x_l  [TTOK*DMOD];
__device__ __half g_qkv_h[TTOK*3072], g_qkv_l[TTOK*3072];
__device__ __half g_ao_h [TTOK*DMOD], g_ao_l [TTOK*DMOD];
__device__ __half g_ffh_h[TTOK*FDIM], g_ffh_l[TTOK*FDIM];
__device__ __half g_mh_h [NE*TTOK*FDIM], g_mh_l [NE*TTOK*FDIM];
__device__ __half g_xn_h [TTOK*DMOD], g_xn_l [TTOK*DMOD];
// fp32 intermediates
__device__ float  g_xf  [TTOK*DMOD];
__device__ float  g_t1f [TTOK*DMOD];
__device__ float  g_moef[TTOK*DMOD];
__device__ float  g_xnf [TTOK*DMOD];
__device__ int    g_cnt [NE];
__device__ int    g_perm[NE*TTOK];
__device__ float  g_pw  [NE*TTOK];

// ---------------- PTX helpers ----------------
__device__ __forceinline__ uint32_t smem_u32(const void* p) {
    return (uint32_t)__cvta_generic_to_shared(p);
}
__device__ __forceinline__ void cp16(void* dst, const void* src, bool valid) {
    asm volatile("cp.async.ca.shared.global [%0], [%1], 16, %2;\n"
                 :: "r"(smem_u32(dst)), "l"(src), "r"(valid ? 16 : 0));
}
__device__ __forceinline__ void cp_commit() { asm volatile("cp.async.commit_group;\n"); }
__device__ __forceinline__ void cp_wait0()  { asm volatile("cp.async.wait_group 0;\n"); }
__device__ __forceinline__ void cp_wait1()  { asm volatile("cp.async.wait_group 1;\n"); }
__device__ __forceinline__ void ldsm4(uint32_t* r, uint32_t a) {
    asm volatile("ldmatrix.sync.aligned.m8n8.x4.shared.b16 {%0,%1,%2,%3},[%4];"
                 : "=r"(r[0]), "=r"(r[1]), "=r"(r[2]), "=r"(r[3]) : "r"(a));
}
__device__ __forceinline__ void ldsm4t(uint32_t* r, uint32_t a) {
    asm volatile("ldmatrix.sync.aligned.m8n8.x4.trans.shared.b16 {%0,%1,%2,%3},[%4];"
                 : "=r"(r[0]), "=r"(r[1]), "=r"(r[2]), "=r"(r[3]) : "r"(a));
}
__device__ __forceinline__ void mma16816(float* c, const uint32_t* a, const uint32_t* b) {
    asm volatile("mma.sync.aligned.m16n8k16.row.col.f32.f16.f16.f32 "
                 "{%0,%1,%2,%3},{%4,%5,%6,%7},{%8,%9},{%0,%1,%2,%3};"
                 : "+f"(c[0]), "+f"(c[1]), "+f"(c[2]), "+f"(c[3])
                 : "r"(a[0]), "r"(a[1]), "r"(a[2]), "r"(a[3]), "r"(b[0]), "r"(b[1]));
}
__device__ __forceinline__ void split2(float v0, float v1, __half2& h2, __half2& l2) {
    __half h0 = __float2half_rn(v0), h1 = __float2half_rn(v1);
    __half l0 = __float2half_rn(v0 - __half2float(h0));
    __half l1 = __float2half_rn(v1 - __half2float(h1));
    h2 = __halves2half2(h0, h1);
    l2 = __halves2half2(l0, l1);
}
__device__ __forceinline__ uint32_t h2u(__half2 v) {
    uint32_t r; memcpy(&r, &v, 4); return r;
}

// ---------------- fp32 -> (hi[, lo]) fp16 split ----------------
__global__ void split_k(const float* __restrict__ s, __half* __restrict__ h,
                        __half* __restrict__ l, long long n4) {
    long long i = (long long)blockIdx.x * blockDim.x + threadIdx.x;
    if (i >= n4) return;
    float4 v = reinterpret_cast<const float4*>(s)[i];
    __half2 h0, l0, h1, l1;
    split2(v.x, v.y, h0, l0);
    split2(v.z, v.w, h1, l1);
    reinterpret_cast<__half2*>(h)[i * 2 + 0] = h0;
    reinterpret_cast<__half2*>(h)[i * 2 + 1] = h1;
    if (l) {
        reinterpret_cast<__half2*>(l)[i * 2 + 0] = l0;
        reinterpret_cast<__half2*>(l)[i * 2 + 1] = l1;
    }
}

// strided split: src[K][N] fp32 -> dst[K][ldd] (hi,lo) at col0; z = layer
__global__ void splits_k(const float* __restrict__ s, __half* __restrict__ dh,
                         __half* __restrict__ dl, int N, int ldd, int col0,
                         long long perz_src, long long perz_dst) {
    const float* sp = s + (long long)blockIdx.z * perz_src;
    __half* dhp = dh + (long long)blockIdx.z * perz_dst;
    __half* dlp = dl + (long long)blockIdx.z * perz_dst;
    long long i = (long long)blockIdx.x * blockDim.x + threadIdx.x;
    long long e = i * 4;
    if (e >= perz_src) return;
    int row = (int)(e / N), col = (int)(e % N);
    float4 v = *reinterpret_cast<const float4*>(sp + e);
    __half2 h0, l0, h1, l1;
    split2(v.x, v.y, h0, l0);
    split2(v.z, v.w, h1, l1);
    __half2* oh = reinterpret_cast<__half2*>(dhp + (long long)row * ldd + col0 + col);
    __half2* ol = reinterpret_cast<__half2*>(dlp + (long long)row * ldd + col0 + col);
    oh[0] = h0; oh[1] = h1;
    ol[0] = l0; ol[1] = l1;
}

// combined qkv bias
__global__ void catb_k(const float* __restrict__ bq, const float* __restrict__ bk,
                       const float* __restrict__ bv, float* __restrict__ dst) {
    int i = blockIdx.x * 256 + threadIdx.x;
    if (i >= NL * DMOD) return;
    int lyr = i / DMOD, d = i % DMOD;
    dst[lyr * 3072 + d]        = bq[i];
    dst[lyr * 3072 + 1024 + d] = bk[i];
    dst[lyr * 3072 + 2048 + d] = bv[i];
}

// ---------------- split-fp16 tensor-core GEMM ----------------
struct HP {
    const __half *Ah, *Al, *Bh, *Bl;
    float* Cf; __half *Chi, *Clo;
    const float* bias;
    int M, N, K, lda, ldb, ldc, bh;
    long long sA1, sA2, sB1, sB2, sC1, sC2, sBias1;
    const int* counts; const int* rowmap; int mapStride;
    const float* rowsc; float* scat; int scat_ld;
};

enum { EP_F32 = 0, EP_SPLIT = 1, EP_SPLIT_RELU = 2, EP_SCATTER = 3 };

// dyn smem bytes: NSTAGE stages of (A-hi [+A-lo] + B-hi [+B-lo])
#define HSB(BM_,NT_,NS_) (2 * (NS_) * ((BM_) * 40 * (((NT_) >= 2) ? 2 : 1) \
                                       + 4352 * (((NT_) == 3) ? 2 : 1)))

// NTERM: 3 = ah*bh + al*bh + ah*bl ; 2 = ah*bh + al*bh ; 1 = ah*bh
// NSTAGE: 2 (two barriers/iter) or 3 (one barrier/iter; use when smem is small)
template<int BM, bool GATHER, int MODE, int NTERM, int NSTAGE>
__global__ __launch_bounds__(256) void hgemm_k(HP p) {
    constexpr int BN = 128, BK = 32;
    constexpr int WROWS = 2, WCOLS = 4;
    constexpr int WM = BM / WROWS, WN = 32, MM = WM / 16, MN = 4;
    constexpr int APAD = 40, BPAD = 136;
    constexpr int ASTG = BM * 40;                      // halves per A stage
    constexpr int NAH  = (NTERM >= 2) ? 2 : 1;
    constexpr int OFF_ALO = NSTAGE * ASTG;             // A-lo base (if present)
    constexpr int OFF_BHI = NSTAGE * ASTG * NAH;
    constexpr int OFF_BLO = OFF_BHI + NSTAGE * 4352;
    extern __shared__ __half sm[];

    const int z  = blockIdx.z;
    const int b2 = z / p.bh, b1 = z % p.bh;
    const __half* Ah = p.Ah + b2 * p.sA2 + b1 * p.sA1;
    const __half* Al = (NTERM >= 2) ? p.Al + b2 * p.sA2 + b1 * p.sA1 : nullptr;
    const __half* Bh = p.Bh + b2 * p.sB2 + b1 * p.sB1;
    const __half* Bl = (NTERM == 3) ? p.Bl + b2 * p.sB2 + b1 * p.sB1 : nullptr;
    const int M = p.counts ? p.counts[z] : p.M;
    const int row0 = blockIdx.y * BM;
    if (row0 >= M) return;
    const int col0 = blockIdx.x * BN;

    const int tid = threadIdx.x;
    const int l   = tid & 31;
    const int wid = tid >> 5;
    const int wr  = wid / WCOLS, wc = wid % WCOLS;

    const int* rmap = (GATHER || MODE == EP_SCATTER)
                      ? p.rowmap + (long long)z * p.mapStride : nullptr;

    float acc[MM][MN][4];
#pragma unroll
    for (int i = 0; i < MM; i++)
#pragma unroll
        for (int j = 0; j < MN; j++)
#pragma unroll
            for (int r = 0; r < 4; r++) acc[i][j][r] = 0.f;

    // A loader: BM*4 16B-chunks per array; 1 (BM=64) or 2 (BM=128) per thread
    const int aRow0 = tid >> 2, aK0 = (tid & 3) * 8;
    const int aRow1 = aRow0 + 64;
    const bool av0 = (row0 + aRow0) < M;
    const bool av1 = (BM == 128) && ((row0 + aRow1) < M);
    long long aB0 = 0, aB1 = 0;
    if (GATHER) {
        aB0 = (long long)(av0 ? rmap[row0 + aRow0] : 0) * p.lda;
        if (BM == 128) aB1 = (long long)(av1 ? rmap[row0 + aRow1] : 0) * p.lda;
    } else {
        aB0 = (long long)(row0 + aRow0) * p.lda;
        if (BM == 128) aB1 = (long long)(row0 + aRow1) * p.lda;
    }
    const int bRow0 = tid >> 4, bN0 = (tid & 15) * 8;
    const int bRow1 = bRow0 + 16;

    auto load_stage = [&](int kt, int st) {
        const int k0 = kt * BK;
        __half* Asth = sm + st * ASTG;
        cp16(Asth + aRow0 * APAD + aK0, Ah + aB0 + k0 + aK0, av0);
        if (BM == 128) cp16(Asth + aRow1 * APAD + aK0, Ah + aB1 + k0 + aK0, av1);
        if (NTERM >= 2) {
            __half* Astl = sm + OFF_ALO + st * ASTG;
            cp16(Astl + aRow0 * APAD + aK0, Al + aB0 + k0 + aK0, av0);
            if (BM == 128) cp16(Astl + aRow1 * APAD + aK0, Al + aB1 + k0 + aK0, av1);
        }
        __half* Bsth = sm + OFF_BHI + st * 4352;
        cp16(Bsth + bRow0 * BPAD + bN0, Bh + (long long)(k0 + bRow0) * p.ldb + col0 + bN0, true);
        cp16(Bsth + bRow1 * BPAD + bN0, Bh + (long long)(k0 + bRow1) * p.ldb + col0 + bN0, true);
        if (NTERM == 3) {
            __half* Bstl = sm + OFF_BLO + st * 4352;
            cp16(Bstl + bRow0 * BPAD + bN0, Bl + (long long)(k0 + bRow0) * p.ldb + col0 + bN0, true);
            cp16(Bstl + bRow1 * BPAD + bN0, Bl + (long long)(k0 + bRow1) * p.ldb + col0 + bN0, true);
        }
        cp_commit();
    };

    auto compute = [&](int st) {
        __half* Asth = sm + st * ASTG;
        __half* Astl = sm + OFF_ALO + st * ASTG;
        __half* Bsth = sm + OFF_BHI + st * 4352;
        __half* Bstl = sm + OFF_BLO + st * 4352;
#pragma unroll
        for (int ks = 0; ks < 2; ks++) {
            uint32_t fah[MM][4], fal[MM][4], fbh[MN][2], fbl[MN][2];
#pragma unroll
            for (int mi = 0; mi < MM; mi++) {
                const int r = wr * WM + mi * 16 + (l & 15);
                const int c = ks * 16 + ((l >> 4) << 3);
                ldsm4(fah[mi], smem_u32(Asth + r * APAD + c));
                if (NTERM >= 2) ldsm4(fal[mi], smem_u32(Astl + r * APAD + c));
            }
#pragma unroll
            for (int nj = 0; nj < MN / 2; nj++) {
                const int r = ks * 16 + (l & 15);
                const int c = wc * WN + nj * 16 + ((l >> 4) << 3);
                uint32_t r4[4];
                ldsm4t(r4, smem_u32(Bsth + r * BPAD + c));
                fbh[2*nj][0] = r4[0]; fbh[2*nj][1] = r4[1];
                fbh[2*nj+1][0] = r4[2]; fbh[2*nj+1][1] = r4[3];
                if (NTERM == 3) {
                    ldsm4t(r4, smem_u32(Bstl + r * BPAD + c));
                    fbl[2*nj][0] = r4[0]; fbl[2*nj][1] = r4[1];
                    fbl[2*nj+1][0] = r4[2]; fbl[2*nj+1][1] = r4[3];
                }
            }
#pragma unroll
            for (int mi = 0; mi < MM; mi++)
#pragma unroll
                for (int ni = 0; ni < MN; ni++) {
                    mma16816(acc[mi][ni], fah[mi], fbh[ni]);
                    if (NTERM >= 2) mma16816(acc[mi][ni], fal[mi], fbh[ni]);
                    if (NTERM == 3) mma16816(acc[mi][ni], fah[mi], fbl[ni]);
                }
        }
    };

    const int nK = p.K / BK;
    if (NSTAGE == 2) {
        load_stage(0, 0);
        for (int kt = 0; kt < nK; kt++) {
            const int st = kt & 1;
            if (kt + 1 < nK) {
                load_stage(kt + 1, st ^ 1);
                cp_wait1();
            } else {
                cp_wait0();
            }
            __syncthreads();
            compute(st);
            __syncthreads();
        }
    } else {
        // 3-stage, ONE barrier per iteration (R10 loop; occupancy-safe here)
        load_stage(0, 0);
        load_stage(1, 1);
        int st = 0;
        for (int kt = 0; kt < nK; kt++) {
            if (kt + 1 < nK) cp_wait1(); else cp_wait0();
            __syncthreads();
            if (kt + 2 < nK) {
                int s2 = st + 2; if (s2 >= 3) s2 -= 3;
                load_stage(kt + 2, s2);
            }
            compute(st);
            if (++st == 3) st = 0;
        }
    }

    const float* bias = p.bias ? p.bias + b1 * p.sBias1 : nullptr;
    float*  Cf  = p.Cf  ? p.Cf  + b2 * p.sC2 + b1 * p.sC1 : nullptr;
    __half* Chi = p.Chi ? p.Chi + b2 * p.sC2 + b1 * p.sC1 : nullptr;
    __half* Clo = p.Clo ? p.Clo + b2 * p.sC2 + b1 * p.sC1 : nullptr;
#pragma unroll
    for (int mi = 0; mi < MM; mi++) {
#pragma unroll
        for (int hh = 0; hh < 2; hh++) {
            const int r = row0 + wr * WM + mi * 16 + (l >> 2) + hh * 8;
            if (r >= M) continue;
#pragma unroll
            for (int ni = 0; ni < MN; ni++) {
                const int c = col0 + wc * WN + ni * 8 + (l & 3) * 2;
                float v0 = acc[mi][ni][hh * 2 + 0];
                float v1 = acc[mi][ni][hh * 2 + 1];
                if (bias) { v0 += bias[c]; v1 += bias[c + 1]; }
                if (MODE == EP_SPLIT_RELU) { v0 = fmaxf(v0, 0.f); v1 = fmaxf(v1, 0.f); }
                if (MODE == EP_SCATTER) {
                    const int tok = rmap[r];
                    const float w = p.rowsc[(long long)z * p.mapStride + r];
                    atomicAdd(p.scat + (long long)tok * p.scat_ld + c,     w * v0);
                    atomicAdd(p.scat + (long long)tok * p.scat_ld + c + 1, w * v1);
                } else if (MODE == EP_F32) {
                    *reinterpret_cast<float2*>(Cf + (long long)r * p.ldc + c) =
                        make_float2(v0, v1);
                } else {
                    __half2 h2, l2;
                    split2(v0, v1, h2, l2);
                    *reinterpret_cast<__half2*>(Chi + (long long)r * p.ldc + c) = h2;
                    *reinterpret_cast<__half2*>(Clo + (long long)r * p.ldc + c) = l2;
                }
            }
        }
    }
}

// ---------------- fused flash attention ----------------
#define FA_SMEM 108544
__global__ __launch_bounds__(256) void fa_k(const __half* __restrict__ qkvh,
                                            const __half* __restrict__ qkvl,
                                            __half* __restrict__ aoh,
                                            __half* __restrict__ aol) {
    extern __shared__ __align__(16) __half fs[];
    __half* Qh  = fs;            // [128][72]
    __half* Ql  = fs + 9216;
    __half* Kth = fs + 18432;    // [64][136] transposed K chunk
    __half* Ktl = fs + 27136;
    __half* Vh  = fs + 35840;    // [128][72] V chunk
    __half* Vl  = fs + 45056;
    const int z = blockIdx.z, b = z / NH, h = z % NH;
    const int q0 = blockIdx.y * 128;
    const int tid = threadIdx.x, l = tid & 31, w = tid >> 5;

#pragma unroll
    for (int i = 0; i < 4; i++) {
        int c = tid + i * 256;
        int row = c >> 3, k8 = (c & 7) * 8;
        long long g = ((long long)(b * SEQ + q0 + row)) * 3072 + h * 64 + k8;
        cp16(Qh + row * 72 + k8, qkvh + g, true);
        cp16(Ql + row * 72 + k8, qkvl + g, true);
    }
    cp_commit();

    float accO[8][4];
#pragma unroll
    for (int i = 0; i < 8; i++)
#pragma unroll
        for (int j = 0; j < 4; j++) accO[i][j] = 0.f;
    float m0 = -1e30f, m1 = -1e30f, s0 = 0.f, s1 = 0.f;

    uint32_t qah[4][4], qal[4][4];

    for (int c = 0; c < 8; c++) {
        const int k0r = c * 128;
        __syncthreads();
#pragma unroll
        for (int i = 0; i < 4; i++) {
            int cc = tid + i * 256;
            int n = cc >> 3, k8 = (cc & 7) * 8;
            long long gk = ((long long)(b * SEQ + k0r + n)) * 3072 + 1024 + h * 64 + k8;
            uint4 rh = *reinterpret_cast<const uint4*>(qkvh + gk);
            uint4 rl = *reinterpret_cast<const uint4*>(qkvl + gk);
            __half hh[8], ll[8];
            memcpy(hh, &rh, 16); memcpy(ll, &rl, 16);
#pragma unroll
            for (int j = 0; j < 8; j++) {
                Kth[(k8 + j) * 136 + n] = hh[j];
                Ktl[(k8 + j) * 136 + n] = ll[j];
            }
            long long gv = ((long long)(b * SEQ + k0r + n)) * 3072 + 2048 + h * 64 + k8;
            cp16(Vh + n * 72 + k8, qkvh + gv, true);
            cp16(Vl + n * 72 + k8, qkvl + gv, true);
        }
        cp_commit();
        cp_wait0();
        __syncthreads();
        if (c == 0) {
#pragma unroll
            for (int ks = 0; ks < 4; ks++) {
                const int r = w * 16 + (l & 15);
                const int cq = ks * 16 + ((l >> 4) << 3);
                ldsm4(qah[ks], smem_u32(Qh + r * 72 + cq));
                ldsm4(qal[ks], smem_u32(Ql + r * 72 + cq));
            }
        }
        float sacc[16][4];
#pragma unroll
        for (int t = 0; t < 16; t++)
#pragma unroll
            for (int j = 0; j < 4; j++) sacc[t][j] = 0.f;
#pragma unroll
        for (int ks = 0; ks < 4; ks++) {
#pragma unroll
            for (int nj = 0; nj < 8; nj++) {
                const int r = ks * 16 + (l & 15);
                const int cc2 = nj * 16 + ((l >> 4) << 3);
                uint32_t r4h[4], r4l[4];
                ldsm4t(r4h, smem_u32(Kth + r * 136 + cc2));
                ldsm4t(r4l, smem_u32(Ktl + r * 136 + cc2));
                uint32_t bh0[2] = {r4h[0], r4h[1]}, bh1[2] = {r4h[2], r4h[3]};
                uint32_t bl0[2] = {r4l[0], r4l[1]}, bl1[2] = {r4l[2], r4l[3]};
                mma16816(sacc[2*nj],   qah[ks], bh0);
                mma16816(sacc[2*nj],   qal[ks], bh0);
                mma16816(sacc[2*nj],   qah[ks], bl0);
                mma16816(sacc[2*nj+1], qah[ks], bh1);
                mma16816(sacc[2*nj+1], qal[ks], bh1);
                mma16816(sacc[2*nj+1], qah[ks], bl1);
            }
        }
        const float scale = 0.125f;
        float nm0 = m0, nm1 = m1;
#pragma unroll
        for (int t = 0; t < 16; t++) {
            sacc[t][0] *= scale; sacc[t][1] *= scale;
            sacc[t][2] *= scale; sacc[t][3] *= scale;
            nm0 = fmaxf(nm0, fmaxf(sacc[t][0], sacc[t][1]));
            nm1 = fmaxf(nm1, fmaxf(sacc[t][2], sacc[t][3]));
        }
        nm0 = fmaxf(nm0, __shfl_xor_sync(0xffffffffu, nm0, 1));
        nm0 = fmaxf(nm0, __shfl_xor_sync(0xffffffffu, nm0, 2));
        nm1 = fmaxf(nm1, __shfl_xor_sync(0xffffffffu, nm1, 1));
        nm1 = fmaxf(nm1, __shfl_xor_sync(0xffffffffu, nm1, 2));
        const float al0 = __expf(m0 - nm0), al1 = __expf(m1 - nm1);
        m0 = nm0; m1 = nm1;
        float ls0 = 0.f, ls1 = 0.f;
#pragma unroll
        for (int t = 0; t < 16; t++) {
            sacc[t][0] = __expf(sacc[t][0] - m0);
            sacc[t][1] = __expf(sacc[t][1] - m0);
            sacc[t][2] = __expf(sacc[t][2] - m1);
            sacc[t][3] = __expf(sacc[t][3] - m1);
            ls0 += sacc[t][0] + sacc[t][1];
            ls1 += sacc[t][2] + sacc[t][3];
        }
        ls0 += __shfl_xor_sync(0xffffffffu, ls0, 1);
        ls0 += __shfl_xor_sync(0xffffffffu, ls0, 2);
        ls1 += __shfl_xor_sync(0xffffffffu, ls1, 1);
        ls1 += __shfl_xor_sync(0xffffffffu, ls1, 2);
        s0 = s0 * al0 + ls0;
        s1 = s1 * al1 + ls1;
#pragma unroll
        for (int t8 = 0; t8 < 8; t8++) {
            accO[t8][0] *= al0; accO[t8][1] *= al0;
            accO[t8][2] *= al1; accO[t8][3] *= al1;
        }
#pragma unroll
        for (int j = 0; j < 8; j++) {
            __half2 ph0, pl0, ph1, pl1, ph2, pl2, ph3, pl3;
            split2(sacc[2*j][0],   sacc[2*j][1],   ph0, pl0);
            split2(sacc[2*j][2],   sacc[2*j][3],   ph1, pl1);
            split2(sacc[2*j+1][0], sacc[2*j+1][1], ph2, pl2);
            split2(sacc[2*j+1][2], sacc[2*j+1][3], ph3, pl3);
            uint32_t pah[4] = {h2u(ph0), h2u(ph1), h2u(ph2), h2u(ph3)};
            uint32_t pal[4] = {h2u(pl0), h2u(pl1), h2u(pl2), h2u(pl3)};
#pragma unroll
            for (int vn = 0; vn < 4; vn++) {
                const int r = j * 16 + (l & 15);
                const int cv = vn * 16 + ((l >> 4) << 3);
                uint32_t r4h[4], r4l[4];
                ldsm4t(r4h, smem_u32(Vh + r * 72 + cv));
                ldsm4t(r4l, smem_u32(Vl + r * 72 + cv));
                uint32_t bh0[2] = {r4h[0], r4h[1]}, bh1[2] = {r4h[2], r4h[3]};
                uint32_t bl0[2] = {r4l[0], r4l[1]}, bl1[2] = {r4l[2], r4l[3]};
                mma16816(accO[2*vn],   pah, bh0);
                mma16816(accO[2*vn],   pal, bh0);
                mma16816(accO[2*vn],   pah, bl0);
                mma16816(accO[2*vn+1], pah, bh1);
                mma16816(accO[2*vn+1], pal, bh1);
                mma16816(accO[2*vn+1], pah, bl1);
            }
        }
    }
    const float inv0 = 1.f / s0, inv1 = 1.f / s1;
    const int r0 = q0 + w * 16 + (l >> 2);
    const int r1 = r0 + 8;
    const long long t0g = (long long)(b * SEQ + r0) * DMOD + h * 64;
    const long long t1g = (long long)(b * SEQ + r1) * DMOD + h * 64;
#pragma unroll
    for (int t8 = 0; t8 < 8; t8++) {
        const int cdim = t8 * 8 + (l & 3) * 2;
        __half2 hh, llh;
        split2(accO[t8][0] * inv0, accO[t8][1] * inv0, hh, llh);
        *reinterpret_cast<__half2*>(aoh + t0g + cdim) = hh;
        *reinterpret_cast<__half2*>(aol + t0g + cdim) = llh;
        split2(accO[t8][2] * inv1, accO[t8][3] * inv1, hh, llh);
        *reinterpret_cast<__half2*>(aoh + t1g + cdim) = hh;
        *reinterpret_cast<__half2*>(aol + t1g + cdim) = llh;
    }
}

// ---------------- embedding + positional encoding ----------------
__global__ void embed_k(const int* __restrict__ src, const float* __restrict__ emb,
                        float* __restrict__ xf, __half* __restrict__ xh,
                        __half* __restrict__ xl) {
    const int t = blockIdx.x;
    const int s = t % SEQ;
    const int tok = src[t];
    const float c = -logf(10000.0f) / (float)DMOD;
    for (int d = threadIdx.x; d < DMOD; d += blockDim.x) {
        const int i = d >> 1;
        const float div = expf((float)(2 * i) * c);
        const float ang = (float)s * div;
        const float pe = (d & 1) ? cosf(ang) : sinf(ang);
        const float v = emb[(long long)tok * DMOD + d] * 32.0f + pe;
        xf[(long long)t * DMOD + d] = v;
        __half h = __float2half_rn(v);
        xh[(long long)t * DMOD + d] = h;
        xl[(long long)t * DMOD + d] = __float2half_rn(v - __half2float(h));
    }
}

// ---------------- layernorm ----------------
__global__ void ln_k(const float* __restrict__ a, const float* __restrict__ res,
                     const float* __restrict__ g, const float* __restrict__ be,
                     float* __restrict__ of, __half* __restrict__ oh,
                     __half* __restrict__ ol) {
    const int row = blockIdx.x;
    const int tid = threadIdx.x;
    float4 v = reinterpret_cast<const float4*>(a + (long long)row * DMOD)[tid];
    if (res) {
        float4 r = reinterpret_cast<const float4*>(res + (long long)row * DMOD)[tid];
        v.x += r.x; v.y += r.y; v.z += r.z; v.w += r.w;
    }
    float s  = v.x + v.y + v.z + v.w;
    float sq = v.x*v.x + v.y*v.y + v.z*v.z + v.w*v.w;
    __shared__ float rs[8], rq[8];
    for (int o = 16; o > 0; o >>= 1) {
        s  += __shfl_xor_sync(0xffffffffu, s,  o);
        sq += __shfl_xor_sync(0xffffffffu, sq, o);
    }
    if ((tid & 31) == 0) { rs[tid >> 5] = s; rq[tid >> 5] = sq; }
    __syncthreads();
    __shared__ float s_mu, s_inv;
    if (tid == 0) {
        float S = 0.f, Q = 0.f;
        for (int i = 0; i < 8; i++) { S += rs[i]; Q += rq[i]; }
        const float mu  = S / (float)DMOD;
        const float var = Q / (float)DMOD - mu * mu;
        s_mu = mu; s_inv = rsqrtf(var + 1e-5f);
    }
    __syncthreads();
    const float mu = s_mu, inv = s_inv;
    const float4 gv = reinterpret_cast<const float4*>(g)[tid];
    const float4 bv = reinterpret_cast<const float4*>(be)[tid];
    float o0 = (v.x - mu) * inv * gv.x + bv.x;
    float o1 = (v.y - mu) * inv * gv.y + bv.y;
    float o2 = (v.z - mu) * inv * gv.z + bv.z;
    float o3 = (v.w - mu) * inv * gv.w + bv.w;
    if (of) reinterpret_cast<float4*>(of + (long long)row * DMOD)[tid] = make_float4(o0, o1, o2, o3);
    __half2 h0, l0, h1, l1;
    split2(o0, o1, h0, l0);
    split2(o2, o3, h1, l1);
    reinterpret_cast<__half2*>(oh + (long long)row * DMOD)[tid * 2 + 0] = h0;
    reinterpret_cast<__half2*>(oh + (long long)row * DMOD)[tid * 2 + 1] = h1;
    reinterpret_cast<__half2*>(ol + (long long)row * DMOD)[tid * 2 + 0] = l0;
    reinterpret_cast<__half2*>(ol + (long long)row * DMOD)[tid * 2 + 1] = l1;
}

// ---------------- zero moe accumulator + counters ----------------
__global__ void zero_k(float* __restrict__ moe, int* __restrict__ cnt) {
    long long i = (long long)blockIdx.x * blockDim.x + threadIdx.x;
    const long long n = (long long)TTOK * DMOD;
    for (; i < n; i += (long long)gridDim.x * blockDim.x) moe[i] = 0.f;
    if (blockIdx.x == 0 && threadIdx.x < NE) cnt[threadIdx.x] = 0;
}

// ---------------- gate ----------------
__global__ void gate_k(const float* __restrict__ x, const float* __restrict__ gw,
                       const float* __restrict__ gb, int* __restrict__ cnt,
                       int* __restrict__ perm, float* __restrict__ pw) {
    const int t = blockIdx.x;
    const int tid = threadIdx.x;
    float acc[NE];
#pragma unroll
    for (int e = 0; e < NE; e++) acc[e] = 0.f;
    for (int d = tid; d < DMOD; d += 256) {
        const float xv = x[(long long)t * DMOD + d];
        const float* grow = gw + (long long)d * NE;
#pragma unroll
        for (int e = 0; e < NE; e++) acc[e] += xv * grow[e];
    }
    __shared__ float sh[NE][8];
    const int lane = tid & 31, wid = tid >> 5;
#pragma unroll
    for (int e = 0; e < NE; e++) {
        float s = acc[e];
        for (int o = 16; o > 0; o >>= 1) s += __shfl_xor_sync(0xffffffffu, s, o);
        if (lane == 0) sh[e][wid] = s;
    }
    __syncthreads();
    if (tid == 0) {
        float lg[NE];
#pragma unroll
        for (int e = 0; e < NE; e++) {
            float s = 0.f;
            for (int w = 0; w < 8; w++) s += sh[e][w];
            lg[e] = s + gb[e];
        }
        int i0 = 0;
        for (int e = 1; e < NE; e++) if (lg[e] > lg[i0]) i0 = e;
        int i1 = (i0 == 0) ? 1 : 0;
        for (int e = 0; e < NE; e++) if (e != i0 && lg[e] > lg[i1]) i1 = e;
        const float e1 = expf(lg[i1] - lg[i0]);
        const float inv = 1.0f / (1.0f + e1);
        int p0 = atomicAdd(&cnt[i0], 1); perm[i0 * TTOK + p0] = t; pw[i0 * TTOK + p0] = inv;
        int p1 = atomicAdd(&cnt[i1], 1); perm[i1 * TTOK + p1] = t; pw[i1 * TTOK + p1] = e1 * inv;
    }
}

// ---------------- host orchestration ----------------
static inline void splitw(const float* s, __half* h, __half* l, long long n) {
    long long n4 = n / 4;
    split_k<<<(unsigned)((n4 + 255) / 256), 256>>>(s, h, l, n4);
}

extern "C" void kernel_launch(void* const* d_in, const int* in_sizes, int n_in,
                              void* d_out, int out_size) {
    (void)in_sizes; (void)n_in; (void)out_size;
    const int*   src    = (const int*)  d_in[0];
    const float* emb    = (const float*)d_in[1];
    const float* Wq     = (const float*)d_in[2];
    const float* bq     = (const float*)d_in[3];
    const float* Wk     = (const float*)d_in[4];
    const float* bk     = (const float*)d_in[5];
    const float* Wv     = (const float*)d_in[6];
    const float* bv     = (const float*)d_in[7];
    const float* Wo     = (const float*)d_in[8];
    const float* bo     = (const float*)d_in[9];
    const float* ln1_g  = (const float*)d_in[10];
    const float* ln1_b  = (const float*)d_in[11];
    const float* W1     = (const float*)d_in[12];
    const float* b1     = (const float*)d_in[13];
    const float* W2     = (const float*)d_in[14];
    const float* b2     = (const float*)d_in[15];
    const float* ln2_g  = (const float*)d_in[16];
    const float* ln2_b  = (const float*)d_in[17];
    const float* gate_W = (const float*)d_in[18];
    const float* gate_b = (const float*)d_in[19];
    const float* eW1    = (const float*)d_in[20];
    const float* eb1    = (const float*)d_in[21];
    const float* eW2    = (const float*)d_in[22];
    const float* eb2    = (const float*)d_in[23];
    const float* fln_g  = (const float*)d_in[24];
    const float* fln_b  = (const float*)d_in[25];
    const float* out_W  = (const float*)d_in[26];
    const float* out_b  = (const float*)d_in[27];

#define SYM(v, s) cudaGetSymbolAddress((void**)&v, s)
    __half *qkvw_h,*qkvw_l,*wo_h,*wo_l,*w1_h,*w1_l,*w2_h,*w2_l,*ew1_h,*ew2_h,*ow_h;
    __half *x_h,*x_l,*qkv_h,*qkv_l,*ao_h,*ao_l;
    __half *ffh_h,*ffh_l,*mh_h,*mh_l,*xn_h,*xn_l;
    float *bqkv,*xf,*t1f,*moef,*xnf,*pw;
    int *cnt,*perm;
    SYM(qkvw_h,g_qkvw_h); SYM(qkvw_l,g_qkvw_l); SYM(bqkv,g_bqkv);
    SYM(wo_h,g_wo_h); SYM(wo_l,g_wo_l);
    SYM(w1_h,g_w1_h); SYM(w1_l,g_w1_l); SYM(w2_h,g_w2_h); SYM(w2_l,g_w2_l);
    SYM(ew1_h,g_ew1_h); SYM(ew2_h,g_ew2_h); SYM(ow_h,g_ow_h);
    SYM(x_h,g_x_h); SYM(x_l,g_x_l); SYM(qkv_h,g_qkv_h); SYM(qkv_l,g_qkv_l);
    SYM(ao_h,g_ao_h); SYM(ao_l,g_ao_l);
    SYM(ffh_h,g_ffh_h); SYM(ffh_l,g_ffh_l); SYM(mh_h,g_mh_h); SYM(mh_l,g_mh_l);
    SYM(xn_h,g_xn_h); SYM(xn_l,g_xn_l);
    SYM(xf,g_xf); SYM(t1f,g_t1f); SYM(moef,g_moef); SYM(xnf,g_xnf);
    SYM(pw,g_pw); SYM(cnt,g_cnt); SYM(perm,g_perm);
#undef SYM

    cudaFuncSetAttribute(fa_k, cudaFuncAttributeMaxDynamicSharedMemorySize, FA_SMEM);
    cudaFuncSetAttribute(hgemm_k<128,false,EP_SPLIT,3,2>,      cudaFuncAttributeMaxDynamicSharedMemorySize, HSB(128,3,2));
    cudaFuncSetAttribute(hgemm_k<128,false,EP_SPLIT_RELU,3,2>, cudaFuncAttributeMaxDynamicSharedMemorySize, HSB(128,3,2));
    cudaFuncSetAttribute(hgemm_k<64, false,EP_F32,3,2>,        cudaFuncAttributeMaxDynamicSharedMemorySize, HSB(64,3,2));
    cudaFuncSetAttribute(hgemm_k<128,true, EP_SPLIT_RELU,1,3>, cudaFuncAttributeMaxDynamicSharedMemorySize, HSB(128,1,3));
    cudaFuncSetAttribute(hgemm_k<128,false,EP_SCATTER,1,3>,    cudaFuncAttributeMaxDynamicSharedMemorySize, HSB(128,1,3));
    cudaFuncSetAttribute(hgemm_k<128,false,EP_F32,1,3>,        cudaFuncAttributeMaxDynamicSharedMemorySize, HSB(128,1,3));

    {
        long long perz = (long long)DMOD * DMOD;
        unsigned blks = (unsigned)((perz / 4 + 255) / 256);
        splits_k<<<dim3(blks,1,NL),256>>>(Wq, qkvw_h, qkvw_l, DMOD, 3072, 0,    perz, (long long)DMOD*3072);
        splits_k<<<dim3(blks,1,NL),256>>>(Wk, qkvw_h, qkvw_l, DMOD, 3072, 1024, perz, (long long)DMOD*3072);
        splits_k<<<dim3(blks,1,NL),256>>>(Wv, qkvw_h, qkvw_l, DMOD, 3072, 2048, perz, (long long)DMOD*3072);
        catb_k<<<(NL*DMOD + 255)/256, 256>>>(bq, bk, bv, bqkv);
    }
    splitw(Wo,  wo_h,  wo_l,  (long long)NL * DMOD * DMOD);
    splitw(W1,  w1_h,  w1_l,  (long long)NL * DMOD * FDIM);
    splitw(W2,  w2_h,  w2_l,  (long long)NL * FDIM * DMOD);
    splitw(eW1, ew1_h, nullptr, (long long)NE * DMOD * FDIM);
    splitw(eW2, ew2_h, nullptr, (long long)NE * FDIM * DMOD);
    splitw(out_W, ow_h, nullptr, (long long)DMOD * VOC);

    embed_k<<<TTOK, 256>>>(src, emb, xf, x_h, x_l);

    for (int l = 0; l < NL; l++) {
        HP p;
        // fused QKV: x @ Wqkv (N=3072)
        p = HP{};
        p.Ah = x_h; p.Al = x_l;
        p.Bh = qkvw_h + (long long)l*DMOD*3072; p.Bl = qkvw_l + (long long)l*DMOD*3072;
        p.Chi = qkv_h; p.Clo = qkv_l; p.bias = bqkv + l*3072;
        p.M = TTOK; p.N = 3072; p.K = DMOD;
        p.lda = DMOD; p.ldb = 3072; p.ldc = 3072; p.bh = 1;
        hgemm_k<128,false,EP_SPLIT,3,2><<<dim3(24,16,1),256,HSB(128,3,2)>>>(p);
        // fused flash attention -> ao (split)
        fa_k<<<dim3(1,8,NBAT*NH),256,FA_SMEM>>>(qkv_h, qkv_l, ao_h, ao_l);
        // ao @ Wo + bo (BM=64: 256 CTAs)
        p = HP{};
        p.Ah = ao_h; p.Al = ao_l;
        p.Bh = wo_h + (long long)l*DMOD*DMOD; p.Bl = wo_l + (long long)l*DMOD*DMOD;
        p.Cf = t1f; p.bias = bo + l*DMOD;
        p.M = TTOK; p.N = DMOD; p.K = DMOD;
        p.lda = DMOD; p.ldb = DMOD; p.ldc = DMOD; p.bh = 1;
        hgemm_k<64,false,EP_F32,3,2><<<dim3(8,32,1),256,HSB(64,3,2)>>>(p);
        ln_k<<<TTOK, 256>>>(t1f, xf, ln1_g + l*DMOD, ln1_b + l*DMOD, xf, x_h, x_l);
        // ffh = relu(x @ W1 + b1)
        p = HP{};
        p.Ah = x_h; p.Al = x_l;
        p.Bh = w1_h + (long long)l*DMOD*FDIM; p.Bl = w1_l + (long long)l*DMOD*FDIM;
        p.Chi = ffh_h; p.Clo = ffh_l; p.bias = b1 + l*FDIM;
        p.M = TTOK; p.N = FDIM; p.K = DMOD;
        p.lda = DMOD; p.ldb = FDIM; p.ldc = FDIM; p.bh = 1;
        hgemm_k<128,false,EP_SPLIT_RELU,3,2><<<dim3(32,16,1),256,HSB(128,3,2)>>>(p);
        // ff = ffh @ W2 + b2 (BM=64: 256 CTAs)
        p = HP{};
        p.Ah = ffh_h; p.Al = ffh_l;
        p.Bh = w2_h + (long long)l*FDIM*DMOD; p.Bl = w2_l + (long long)l*FDIM*DMOD;
        p.Cf = t1f; p.bias = b2 + l*DMOD;
        p.M = TTOK; p.N = DMOD; p.K = FDIM;
        p.lda = FDIM; p.ldb = DMOD; p.ldc = DMOD; p.bh = 1;
        hgemm_k<64,false,EP_F32,3,2><<<dim3(8,32,1),256,HSB(64,3,2)>>>(p);
        ln_k<<<TTOK, 256>>>(t1f, xf, ln2_g + l*DMOD, ln2_b + l*DMOD, xf, x_h, x_l);
    }

    // MoE (post-gate: NTERM=1 hi-only experts, 3-stage pipeline)
    zero_k<<<2048, 256>>>(moef, cnt);
    gate_k<<<TTOK, 256>>>(xf, gate_W, gate_b, cnt, perm, pw);
    {
        HP p = HP{};
        p.Ah = x_h; p.Bh = ew1_h;
        p.Chi = mh_h; p.Clo = mh_l; p.bias = eb1;
        p.M = TTOK; p.N = FDIM; p.K = DMOD;
        p.lda = DMOD; p.ldb = FDIM; p.ldc = FDIM; p.bh = NE;
        p.sB1 = (long long)DMOD * FDIM; p.sC1 = (long long)TTOK * FDIM; p.sBias1 = FDIM;
        p.counts = cnt; p.rowmap = perm; p.mapStride = TTOK;
        hgemm_k<128,true,EP_SPLIT_RELU,1,3><<<dim3(32,16,NE),256,HSB(128,1,3)>>>(p);
    }
    {
        HP p = HP{};
        p.Ah = mh_h; p.Bh = ew2_h; p.bias = eb2;
        p.M = TTOK; p.N = DMOD; p.K = FDIM;
        p.lda = FDIM; p.ldb = DMOD; p.bh = NE;
        p.sA1 = (long long)TTOK * FDIM; p.sB1 = (long long)FDIM * DMOD; p.sBias1 = DMOD;
        p.counts = cnt; p.rowmap = perm; p.mapStride = TTOK;
        p.rowsc = pw; p.scat = moef; p.scat_ld = DMOD;
        hgemm_k<128,false,EP_SCATTER,1,3><<<dim3(8,16,NE),256,HSB(128,1,3)>>>(p);
    }
    ln_k<<<TTOK, 256>>>(moef, nullptr, fln_g, fln_b, xnf, xn_h, xn_l);
    // output projection -> d_out (hi-only NTERM=1, 3-stage)
    {
        HP p = HP{};
        p.Ah = xn_h; p.Bh = ow_h;
        p.Cf = (float*)d_out; p.bias = out_b;
        p.M = TTOK; p.N = VOC; p.K = DMOD;
        p.lda = DMOD; p.ldb = VOC; p.ldc = VOC; p.bh = 1;
        hgemm_k<128,false,EP_F32,1,3><<<dim3(250,16,1),256,HSB(128,1,3)>>>(p);
    }
}